// round 5
// baseline (speedup 1.0000x reference)
#include <cuda_runtime.h>
#include <cuda_bf16.h>
#include <math.h>
#include <stdint.h>

// Problem constants
#define Bz 4
#define Sz 2048
#define Dz 1024
#define Fz 4096
#define BSz (Bz*Sz)   // 8192

// GEMM tiling (mma.sync path)
#define BM 128
#define BN 256
#define BK 32
#define NTHREADS 512
#define TSTRIDE 40                       // padded row stride in bf16 elems (80B)
#define TILE_A (128*TSTRIDE*2)           // 10240 B per A plane
#define TILE_B (256*TSTRIDE*2)           // 20480 B per B plane
#define STAGE_BYTES (2*TILE_A + 2*TILE_B) // 61440 B
#define NSTAGE 3
#define SMEM_TOTAL (NSTAGE*STAGE_BYTES)  // 184320 B

// ---------------- scratch (static device globals; no allocation) ----------------
#define AL __align__(256)
__device__ AL __nv_bfloat16 s_ln1h[(size_t)BSz*Dz], s_ln1l[(size_t)BSz*Dz];
__device__ AL __nv_bfloat16 s_qwTh[(size_t)Dz*Dz],  s_qwTl[(size_t)Dz*Dz];
__device__ AL __nv_bfloat16 s_kwTh[(size_t)Dz*Dz],  s_kwTl[(size_t)Dz*Dz];
__device__ AL __nv_bfloat16 s_vwTh[(size_t)Dz*Dz],  s_vwTl[(size_t)Dz*Dz];
__device__ AL __nv_bfloat16 s_qh[(size_t)BSz*Dz],   s_ql[(size_t)BSz*Dz];
__device__ AL __nv_bfloat16 s_kh[(size_t)BSz*Dz],   s_kl[(size_t)BSz*Dz];
__device__ AL float         s_v [(size_t)BSz*Dz];
__device__ AL __nv_bfloat16 s_vTh[(size_t)Bz*Dz*Sz], s_vTl[(size_t)Bz*Dz*Sz];
__device__ AL float         s_sc[(size_t)Bz*Sz*Sz];
__device__ AL __nv_bfloat16 s_ph[(size_t)Bz*Sz*Sz], s_pl[(size_t)Bz*Sz*Sz];
__device__ AL float         s_x1[(size_t)BSz*Dz];
__device__ AL __nv_bfloat16 s_ln2h[(size_t)BSz*Dz], s_ln2l[(size_t)BSz*Dz];
__device__ AL __nv_bfloat16 s_w1Th[(size_t)Fz*Dz],  s_w1Tl[(size_t)Fz*Dz];
__device__ AL __nv_bfloat16 s_w2Th[(size_t)Dz*Fz],  s_w2Tl[(size_t)Dz*Fz];
__device__ AL __nv_bfloat16 s_hh[(size_t)BSz*Fz],   s_hl[(size_t)BSz*Fz];

// ---------------- PTX helpers (arch-portable: cp.async + ldmatrix + mma.sync) ----------------
__device__ __forceinline__ uint32_t smem_u32(const void* p) {
    uint32_t a;
    asm("{ .reg .u64 t; cvta.to.shared.u64 t, %1; cvt.u32.u64 %0, t; }" : "=r"(a) : "l"(p));
    return a;
}
__device__ __forceinline__ void cp16(uint32_t dst, const void* src) {
    asm volatile("cp.async.cg.shared.global [%0], [%1], 16;" :: "r"(dst), "l"(src));
}
__device__ __forceinline__ void cp_commit() { asm volatile("cp.async.commit_group;" ::: "memory"); }
__device__ __forceinline__ void cp_wait1()  { asm volatile("cp.async.wait_group 1;" ::: "memory"); }

__device__ __forceinline__ void ldm_x4(uint32_t* r, uint32_t addr) {
    asm volatile("ldmatrix.sync.aligned.m8n8.x4.shared.b16 {%0,%1,%2,%3}, [%4];"
                 : "=r"(r[0]), "=r"(r[1]), "=r"(r[2]), "=r"(r[3]) : "r"(addr));
}
__device__ __forceinline__ void mma16816(float* c, const uint32_t* a, const uint32_t* b) {
    asm volatile(
        "mma.sync.aligned.m16n8k16.row.col.f32.bf16.bf16.f32 "
        "{%0,%1,%2,%3}, {%4,%5,%6,%7}, {%8,%9}, {%0,%1,%2,%3};"
        : "+f"(c[0]), "+f"(c[1]), "+f"(c[2]), "+f"(c[3])
        : "r"(a[0]), "r"(a[1]), "r"(a[2]), "r"(a[3]), "r"(b[0]), "r"(b[1]));
}
__device__ __forceinline__ uint32_t pack_bf16x2(float a, float b) {
    __nv_bfloat16 ha = __float2bfloat16(a), hb = __float2bfloat16(b);
    return ((uint32_t)__bfloat16_as_ushort(hb) << 16) | (uint32_t)__bfloat16_as_ushort(ha);
}

// ---------------- reductions ----------------
__device__ __forceinline__ float warp_sum(float v) {
    #pragma unroll
    for (int o = 16; o > 0; o >>= 1) v += __shfl_xor_sync(0xffffffffu, v, o);
    return v;
}
__device__ __forceinline__ float warp_max(float v) {
    #pragma unroll
    for (int o = 16; o > 0; o >>= 1) v = fmaxf(v, __shfl_xor_sync(0xffffffffu, v, o));
    return v;
}
__device__ __forceinline__ float block_sum(float v, float* sm) {
    int wid = threadIdx.x >> 5, lid = threadIdx.x & 31;
    v = warp_sum(v);
    if (lid == 0) sm[wid] = v;
    __syncthreads();
    float r = (lid < 8) ? sm[lid] : 0.0f;
    r = warp_sum(r);
    r = __shfl_sync(0xffffffffu, r, 0);
    __syncthreads();
    return r;
}
__device__ __forceinline__ float block_max(float v, float* sm) {
    int wid = threadIdx.x >> 5, lid = threadIdx.x & 31;
    v = warp_max(v);
    if (lid == 0) sm[wid] = v;
    __syncthreads();
    float r = (lid < 8) ? sm[lid] : -INFINITY;
    r = warp_max(r);
    r = __shfl_sync(0xffffffffu, r, 0);
    __syncthreads();
    return r;
}

// ---------------- LN writing split planes ----------------
__global__ void ln_split_kernel(const float* __restrict__ x,
                                const float* __restrict__ gamma,
                                const float* __restrict__ beta,
                                __nv_bfloat16* __restrict__ hi,
                                __nv_bfloat16* __restrict__ lo) {
    __shared__ float sm[8];
    size_t row = blockIdx.x;
    const float* xr = x + row * Dz;
    int t = threadIdx.x;
    float v[4];
    float s = 0.f, s2 = 0.f;
    #pragma unroll
    for (int i = 0; i < 4; i++) {
        float val = xr[t + i * 256];
        v[i] = val; s += val; s2 += val * val;
    }
    float tot  = block_sum(s,  sm);
    float tot2 = block_sum(s2, sm);
    float mean = tot * (1.0f / Dz);
    float var  = tot2 * (1.0f / Dz) - mean * mean;
    float inv  = rsqrtf(var + 1e-5f);
    #pragma unroll
    for (int i = 0; i < 4; i++) {
        int c = t + i * 256;
        float y = gamma[c] * ((v[i] - mean) * inv) + beta[c];
        __nv_bfloat16 h = __float2bfloat16(y);
        hi[row * Dz + c] = h;
        lo[row * Dz + c] = __float2bfloat16(y - __bfloat162float(h));
    }
}

// ---------------- transpose + split: in fp32 [R,C] -> planes [C,R] ----------------
__global__ void transpose_split_kernel(const float* __restrict__ in,
                                       __nv_bfloat16* __restrict__ hi,
                                       __nv_bfloat16* __restrict__ lo,
                                       int R, int C, long sIn, long sOut) {
    __shared__ float t[32][33];
    in += (size_t)blockIdx.z * sIn;
    hi += (size_t)blockIdx.z * sOut;
    lo += (size_t)blockIdx.z * sOut;
    int rb = blockIdx.y * 32, cb = blockIdx.x * 32;
    int tx = threadIdx.x, ty = threadIdx.y;
    #pragma unroll
    for (int k = 0; k < 4; k++)
        t[ty + 8 * k][tx] = in[(size_t)(rb + ty + 8 * k) * C + cb + tx];
    __syncthreads();
    #pragma unroll
    for (int k = 0; k < 4; k++) {
        float v = t[tx][ty + 8 * k];
        int orow = cb + ty + 8 * k, ocol = rb + tx;
        __nv_bfloat16 h = __float2bfloat16(v);
        hi[(size_t)orow * R + ocol] = h;
        lo[(size_t)orow * R + ocol] = __float2bfloat16(v - __bfloat162float(h));
    }
}

// ---------------- causal softmax -> split probs (masked-chunk load skip) ----------------
__global__ void softmax_split_kernel(const float* __restrict__ sc,
                                     __nv_bfloat16* __restrict__ Phi,
                                     __nv_bfloat16* __restrict__ Plo) {
    __shared__ float sm[8];
    int row = blockIdx.x;
    int r = row & (Sz - 1);
    const float* src = sc + (size_t)row * Sz;
    int t = threadIdx.x;
    float v[8];
    float m = -INFINITY;
    #pragma unroll
    for (int i = 0; i < 8; i++) {
        int c = t + i * 256;
        float val = -INFINITY;
        if (i * 256 <= r) {               // chunk has at least one unmasked col
            val = src[c];
            val = (c <= r) ? val : -INFINITY;
        }
        v[i] = val;
        m = fmaxf(m, val);
    }
    m = block_max(m, sm);
    float s = 0.f;
    #pragma unroll
    for (int i = 0; i < 8; i++) {
        v[i] = expf(v[i] - m);
        s += v[i];
    }
    s = block_sum(s, sm);
    float inv = 1.0f / s;
    #pragma unroll
    for (int i = 0; i < 8; i++) {
        int c = t + i * 256;
        float p = v[i] * inv;
        __nv_bfloat16 h = __float2bfloat16(p);
        Phi[(size_t)row * Sz + c] = h;
        Plo[(size_t)row * Sz + c] = __float2bfloat16(p - __bfloat162float(h));
    }
}

// ---------------- split-bf16 GEMM via mma.sync (HMMA) ----------------
// C[M,N] = alpha * sum_k A[m,k]*Bt[n,k]  (A,Bt as hi/lo bf16 planes, K-major)
// OUTM: 0 = fp32 C, 1 = split planes (Chi/Clo)
// 512 threads, BM=128, BN=256, BK=32, 3-stage cp.async pipeline, 1 barrier/stage.
template<int OUTM, bool BIAS_, bool RELU_, bool RES_, bool CAUSAL_, bool KTRIM_>
__global__ void __launch_bounds__(NTHREADS, 1)
tc_gemm(const __nv_bfloat16* __restrict__ Ahi, const __nv_bfloat16* __restrict__ Alo,
        const __nv_bfloat16* __restrict__ Bhi, const __nv_bfloat16* __restrict__ Blo,
        float* __restrict__ Cf,
        __nv_bfloat16* __restrict__ Chi, __nv_bfloat16* __restrict__ Clo,
        const float* __restrict__ bias, const float* __restrict__ res,
        int M, int N, int K, float alpha, long sA, long sB, long sC)
{
    extern __shared__ char dynsmem[];
    const int bm = blockIdx.y * BM;
    const int bn = blockIdx.x * BN;
    if (CAUSAL_ && bn >= bm + BM) return;   // fully masked tile (softmax re-masks anyway)

    const int tid  = threadIdx.x;
    const int wid  = tid >> 5;
    const int lane = tid & 31;
    const int warp_m = wid >> 2;     // 0..3  (rows, 32 each)
    const int warp_n = wid & 3;      // 0..3  (cols, 64 each)

    Ahi += (size_t)blockIdx.z * sA;  Alo += (size_t)blockIdx.z * sA;
    Bhi += (size_t)blockIdx.z * sB;  Blo += (size_t)blockIdx.z * sB;
    if (OUTM == 0) Cf += (size_t)blockIdx.z * sC;
    else { Chi += (size_t)blockIdx.z * sC; Clo += (size_t)blockIdx.z * sC; }
    if (RES_) res += (size_t)blockIdx.z * sC;

    const uint32_t smem_base = smem_u32(dynsmem);

    const int kmax = KTRIM_ ? min(K, bm + BM) : K;
    const int nst  = kmax >> 5;      // BK=32

    // per-stage cp.async: A 1024 + B 2048 chunks of 16B, 6 per thread
    auto issue_loads = [&](int s) {
        uint32_t sb = smem_base + (uint32_t)(s % NSTAGE) * STAGE_BYTES;
        int kt = s * BK;
        #pragma unroll
        for (int i = 0; i < 2; i++) {            // A: 1024 chunks
            int id = i * NTHREADS + tid;         // 0..1023
            const __nv_bfloat16* src = (id < 512) ? Ahi : Alo;
            uint32_t off = (id < 512) ? 0u : (uint32_t)TILE_A;
            int r  = (id >> 2) & 127;
            int c4 = id & 3;
            cp16(sb + off + (uint32_t)(r * TSTRIDE + c4 * 8) * 2,
                 src + (size_t)(bm + r) * K + kt + c4 * 8);
        }
        #pragma unroll
        for (int i = 0; i < 4; i++) {            // B: 2048 chunks
            int id = i * NTHREADS + tid;         // 0..2047
            const __nv_bfloat16* src = (id < 1024) ? Bhi : Blo;
            uint32_t off = 2u * TILE_A + ((id < 1024) ? 0u : (uint32_t)TILE_B);
            int r  = (id >> 2) & 255;
            int c4 = id & 3;
            cp16(sb + off + (uint32_t)(r * TSTRIDE + c4 * 8) * 2,
                 src + (size_t)(bn + r) * K + kt + c4 * 8);
        }
    };

    float acc[2][8][4];
    #pragma unroll
    for (int i = 0; i < 2; i++)
        #pragma unroll
        for (int j = 0; j < 8; j++)
            #pragma unroll
            for (int k = 0; k < 4; k++) acc[i][j][k] = 0.f;

    issue_loads(0); cp_commit();
    if (nst > 1) issue_loads(1);
    cp_commit();

    for (int s = 0; s < nst; s++) {
        cp_wait1();                  // stage s ready (groups retire in order)
        __syncthreads();             // everyone done computing stage s-1 -> its buffer reusable

        if (s + 2 < nst) issue_loads(s + 2);
        cp_commit();                 // always commit (empty groups keep wait_group semantics)

        uint32_t sb = smem_base + (uint32_t)(s % NSTAGE) * STAGE_BYTES;
        uint32_t aH = sb, aL = sb + TILE_A;
        uint32_t bH = sb + 2u * TILE_A, bL = bH + TILE_B;

        #pragma unroll
        for (int k16 = 0; k16 < BK; k16 += 16) {
            uint32_t ah[2][4], al[2][4];
            #pragma unroll
            for (int mi = 0; mi < 2; mi++) {
                uint32_t arow = (uint32_t)(warp_m * 32 + mi * 16 + (lane & 15));
                uint32_t aoff = (arow * TSTRIDE + (uint32_t)(k16 + (lane >> 4) * 8)) * 2;
                ldm_x4(ah[mi], aH + aoff);
                ldm_x4(al[mi], aL + aoff);
            }
            #pragma unroll
            for (int j = 0; j < 4; j++) {
                uint32_t brow = (uint32_t)(warp_n * 64 + j * 16 + ((lane >> 4) * 8) + (lane & 7));
                uint32_t boff = (brow * TSTRIDE + (uint32_t)(k16 + ((lane >> 3) & 1) * 8)) * 2;
                uint32_t bh[4], bl[4];
                ldm_x4(bh, bH + boff);
                ldm_x4(bl, bL + boff);
                #pragma unroll
                for (int sub = 0; sub < 2; sub++) {
                    int ni = j * 2 + sub;
                    #pragma unroll
                    for (int mi = 0; mi < 2; mi++) {
                        mma16816(acc[mi][ni], ah[mi], bh + sub * 2);  // hi*hi
                        mma16816(acc[mi][ni], ah[mi], bl + sub * 2);  // hi*lo
                        mma16816(acc[mi][ni], al[mi], bh + sub * 2);  // lo*hi
                    }
                }
            }
        }
    }

    // ---------------- epilogue from register accumulators ----------------
    const int g = lane >> 2, t4 = lane & 3;
    #pragma unroll
    for (int mi = 0; mi < 2; mi++) {
        #pragma unroll
        for (int ni = 0; ni < 8; ni++) {
            int col = bn + warp_n * 64 + ni * 8 + t4 * 2;
            #pragma unroll
            for (int half = 0; half < 2; half++) {
                int row = bm + warp_m * 32 + mi * 16 + g + half * 8;
                float v0 = acc[mi][ni][half * 2 + 0] * alpha;
                float v1 = acc[mi][ni][half * 2 + 1] * alpha;
                if (BIAS_) { v0 += bias[col]; v1 += bias[col + 1]; }
                if (RELU_) { v0 = fmaxf(v0, 0.f); v1 = fmaxf(v1, 0.f); }
                if (RES_) {
                    float2 rv = *(const float2*)(res + (size_t)row * N + col);
                    v0 += rv.x; v1 += rv.y;
                }
                if (OUTM == 0) {
                    float2 o; o.x = v0; o.y = v1;
                    *(float2*)(Cf + (size_t)row * N + col) = o;
                } else {
                    uint32_t hp = pack_bf16x2(v0, v1);
                    float l0 = v0 - __bfloat162float(__float2bfloat16(v0));
                    float l1 = v1 - __bfloat162float(__float2bfloat16(v1));
                    uint32_t lp = pack_bf16x2(l0, l1);
                    *(uint32_t*)(Chi + (size_t)row * N + col) = hp;
                    *(uint32_t*)(Clo + (size_t)row * N + col) = lp;
                }
            }
        }
    }
}

// ---------------- launcher ----------------
extern "C" void kernel_launch(void* const* d_in, const int* in_sizes, int n_in,
                              void* d_out, int out_size) {
    (void)in_sizes; (void)n_in; (void)out_size;
    const float* x      = (const float*)d_in[0];
    const float* Qw     = (const float*)d_in[1];
    const float* Kw     = (const float*)d_in[2];
    const float* Vw     = (const float*)d_in[3];
    const float* w1     = (const float*)d_in[4];
    const float* b1     = (const float*)d_in[5];
    const float* w2     = (const float*)d_in[6];
    const float* b2     = (const float*)d_in[7];
    const float* gamma1 = (const float*)d_in[8];
    const float* beta1  = (const float*)d_in[9];
    const float* gamma2 = (const float*)d_in[10];
    const float* beta2  = (const float*)d_in[11];
    float* out = (float*)d_out;

    __nv_bfloat16 *ln1h,*ln1l,*qwTh,*qwTl,*kwTh,*kwTl,*vwTh,*vwTl;
    __nv_bfloat16 *qh,*ql,*kh,*kl,*vTh,*vTl,*ph,*pl,*ln2h,*ln2l;
    __nv_bfloat16 *w1Th,*w1Tl,*w2Th,*w2Tl,*hh,*hl;
    float *vf,*sc,*x1;
    cudaGetSymbolAddress((void**)&ln1h, s_ln1h); cudaGetSymbolAddress((void**)&ln1l, s_ln1l);
    cudaGetSymbolAddress((void**)&qwTh, s_qwTh); cudaGetSymbolAddress((void**)&qwTl, s_qwTl);
    cudaGetSymbolAddress((void**)&kwTh, s_kwTh); cudaGetSymbolAddress((void**)&kwTl, s_kwTl);
    cudaGetSymbolAddress((void**)&vwTh, s_vwTh); cudaGetSymbolAddress((void**)&vwTl, s_vwTl);
    cudaGetSymbolAddress((void**)&qh, s_qh);     cudaGetSymbolAddress((void**)&ql, s_ql);
    cudaGetSymbolAddress((void**)&kh, s_kh);     cudaGetSymbolAddress((void**)&kl, s_kl);
    cudaGetSymbolAddress((void**)&vf, s_v);
    cudaGetSymbolAddress((void**)&vTh, s_vTh);   cudaGetSymbolAddress((void**)&vTl, s_vTl);
    cudaGetSymbolAddress((void**)&sc, s_sc);
    cudaGetSymbolAddress((void**)&ph, s_ph);     cudaGetSymbolAddress((void**)&pl, s_pl);
    cudaGetSymbolAddress((void**)&x1, s_x1);
    cudaGetSymbolAddress((void**)&ln2h, s_ln2h); cudaGetSymbolAddress((void**)&ln2l, s_ln2l);
    cudaGetSymbolAddress((void**)&w1Th, s_w1Th); cudaGetSymbolAddress((void**)&w1Tl, s_w1Tl);
    cudaGetSymbolAddress((void**)&w2Th, s_w2Th); cudaGetSymbolAddress((void**)&w2Tl, s_w2Tl);
    cudaGetSymbolAddress((void**)&hh, s_hh);     cudaGetSymbolAddress((void**)&hl, s_hl);

    cudaFuncSetAttribute(tc_gemm<1,false,false,false,false,false>, cudaFuncAttributeMaxDynamicSharedMemorySize, SMEM_TOTAL);
    cudaFuncSetAttribute(tc_gemm<0,false,false,false,false,false>, cudaFuncAttributeMaxDynamicSharedMemorySize, SMEM_TOTAL);
    cudaFuncSetAttribute(tc_gemm<0,false,false,false,true ,false>, cudaFuncAttributeMaxDynamicSharedMemorySize, SMEM_TOTAL);
    cudaFuncSetAttribute(tc_gemm<0,false,false,true ,false,true >, cudaFuncAttributeMaxDynamicSharedMemorySize, SMEM_TOTAL);
    cudaFuncSetAttribute(tc_gemm<1,true ,true ,false,false,false>, cudaFuncAttributeMaxDynamicSharedMemorySize, SMEM_TOTAL);
    cudaFuncSetAttribute(tc_gemm<0,true ,false,true ,false,false>, cudaFuncAttributeMaxDynamicSharedMemorySize, SMEM_TOTAL);

    const float scale = 1.0f / 32.0f;

    // 1) LN1 -> split planes
    ln_split_kernel<<<BSz, 256>>>(x, gamma1, beta1, ln1h, ln1l);

    // 2) weight transposes -> split planes
    {
        dim3 blk(32, 8);
        transpose_split_kernel<<<dim3(Dz/32, Dz/32, 1), blk>>>(Qw, qwTh, qwTl, Dz, Dz, 0, 0);
        transpose_split_kernel<<<dim3(Dz/32, Dz/32, 1), blk>>>(Kw, kwTh, kwTl, Dz, Dz, 0, 0);
        transpose_split_kernel<<<dim3(Dz/32, Dz/32, 1), blk>>>(Vw, vwTh, vwTl, Dz, Dz, 0, 0);
        transpose_split_kernel<<<dim3(Fz/32, Dz/32, 1), blk>>>(w1, w1Th, w1Tl, Dz, Fz, 0, 0);
        transpose_split_kernel<<<dim3(Dz/32, Fz/32, 1), blk>>>(w2, w2Th, w2Tl, Fz, Dz, 0, 0);
    }

    // 3) Q, K projections -> split planes; V -> fp32
    {
        dim3 grid(Dz/BN, BSz/BM, 1);
        tc_gemm<1,false,false,false,false,false><<<grid, NTHREADS, SMEM_TOTAL>>>(
            ln1h, ln1l, qwTh, qwTl, nullptr, qh, ql, nullptr, nullptr,
            BSz, Dz, Dz, 1.f, 0, 0, 0);
        tc_gemm<1,false,false,false,false,false><<<grid, NTHREADS, SMEM_TOTAL>>>(
            ln1h, ln1l, kwTh, kwTl, nullptr, kh, kl, nullptr, nullptr,
            BSz, Dz, Dz, 1.f, 0, 0, 0);
        tc_gemm<0,false,false,false,false,false><<<grid, NTHREADS, SMEM_TOTAL>>>(
            ln1h, ln1l, vwTh, vwTl, vf, nullptr, nullptr, nullptr, nullptr,
            BSz, Dz, Dz, 1.f, 0, 0, 0);
    }

    // 4) V^T split planes (per batch [D,S])
    {
        dim3 blk(32, 8);
        transpose_split_kernel<<<dim3(Dz/32, Sz/32, Bz), blk>>>(
            vf, vTh, vTl, Sz, Dz, (long)Sz*Dz, (long)Dz*Sz);
    }

    // 5) scores = Q@K^T * scale (causal tile-skip), fp32 out
    {
        dim3 grid(Sz/BN, Sz/BM, Bz);
        tc_gemm<0,false,false,false,true,false><<<grid, NTHREADS, SMEM_TOTAL>>>(
            qh, ql, kh, kl, sc, nullptr, nullptr, nullptr, nullptr,
            Sz, Sz, Dz, scale, (long)Sz*Dz, (long)Sz*Dz, (long)Sz*Sz);
    }

    // 6) causal softmax -> split probs
    softmax_split_kernel<<<BSz, 256>>>(sc, ph, pl);

    // 7) x1 = x + P@V   (K trimmed by causality)
    {
        dim3 grid(Dz/BN, Sz/BM, Bz);
        tc_gemm<0,false,false,true,false,true><<<grid, NTHREADS, SMEM_TOTAL>>>(
            ph, pl, vTh, vTl, x1, nullptr, nullptr, nullptr, x,
            Sz, Dz, Sz, 1.f, (long)Sz*Sz, (long)Dz*Sz, (long)Sz*Dz);
    }

    // 8) LN2 -> split planes
    ln_split_kernel<<<BSz, 256>>>(x1, gamma2, beta2, ln2h, ln2l);

    // 9) h = relu(ln2 @ w1 + b1) -> split planes
    {
        dim3 grid(Fz/BN, BSz/BM, 1);
        tc_gemm<1,true,true,false,false,false><<<grid, NTHREADS, SMEM_TOTAL>>>(
            ln2h, ln2l, w1Th, w1Tl, nullptr, hh, hl, b1, nullptr,
            BSz, Fz, Dz, 1.f, 0, 0, 0);
    }

    // 10) out = x1 + h @ w2 + b2
    {
        dim3 grid(Dz/BN, BSz/BM, 1);
        tc_gemm<0,true,false,true,false,false><<<grid, NTHREADS, SMEM_TOTAL>>>(
            hh, hl, w2Th, w2Tl, out, nullptr, nullptr, b2, x1,
            BSz, Dz, Fz, 1.f, 0, 0, 0);
    }
}

// round 6
// speedup vs baseline: 1.0187x; 1.0187x over previous
#include <cuda_runtime.h>
#include <cuda_bf16.h>
#include <math.h>
#include <stdint.h>

// Problem constants
#define Bz 4
#define Sz 2048
#define Dz 1024
#define Fz 4096
#define BSz (Bz*Sz)   // 8192

// GEMM tiling (mma.sync path) — R4 shape: 2 CTAs/SM
#define BM 128
#define BN 128
#define BK 32
#define TSTRIDE 40                    // padded row stride in bf16 elems (80B)
#define TILE_BYTES (128*TSTRIDE*2)    // 10240 B per plane tile
#define STAGE_BYTES (4*TILE_BYTES)    // Ah, Al, Bh, Bl
#define SMEM_TOTAL (2*STAGE_BYTES)    // 81920 B

// ---------------- scratch (static device globals; no allocation) ----------------
#define AL __align__(256)
__device__ AL __nv_bfloat16 s_ln1h[(size_t)BSz*Dz], s_ln1l[(size_t)BSz*Dz];
__device__ AL __nv_bfloat16 s_qwTh[(size_t)Dz*Dz],  s_qwTl[(size_t)Dz*Dz];
__device__ AL __nv_bfloat16 s_kwTh[(size_t)Dz*Dz],  s_kwTl[(size_t)Dz*Dz];
__device__ AL __nv_bfloat16 s_vwTh[(size_t)Dz*Dz],  s_vwTl[(size_t)Dz*Dz];
__device__ AL __nv_bfloat16 s_qh[(size_t)BSz*Dz],   s_ql[(size_t)BSz*Dz];
__device__ AL __nv_bfloat16 s_kh[(size_t)BSz*Dz],   s_kl[(size_t)BSz*Dz];
__device__ AL float         s_v [(size_t)BSz*Dz];
__device__ AL __nv_bfloat16 s_vTh[(size_t)Bz*Dz*Sz], s_vTl[(size_t)Bz*Dz*Sz];
__device__ AL float         s_sc[(size_t)Bz*Sz*Sz];
__device__ AL __nv_bfloat16 s_ph[(size_t)Bz*Sz*Sz], s_pl[(size_t)Bz*Sz*Sz];
__device__ AL float         s_x1[(size_t)BSz*Dz];
__device__ AL __nv_bfloat16 s_ln2h[(size_t)BSz*Dz], s_ln2l[(size_t)BSz*Dz];
__device__ AL __nv_bfloat16 s_w1Th[(size_t)Fz*Dz],  s_w1Tl[(size_t)Fz*Dz];
__device__ AL __nv_bfloat16 s_w2Th[(size_t)Dz*Fz],  s_w2Tl[(size_t)Dz*Fz];
__device__ AL __nv_bfloat16 s_hh[(size_t)BSz*Fz],   s_hl[(size_t)BSz*Fz];

// ---------------- PTX helpers (arch-portable: cp.async + ldmatrix + mma.sync) ----------------
__device__ __forceinline__ uint32_t smem_u32(const void* p) {
    uint32_t a;
    asm("{ .reg .u64 t; cvta.to.shared.u64 t, %1; cvt.u32.u64 %0, t; }" : "=r"(a) : "l"(p));
    return a;
}
__device__ __forceinline__ void cp16(uint32_t dst, const void* src) {
    asm volatile("cp.async.cg.shared.global [%0], [%1], 16;" :: "r"(dst), "l"(src));
}
__device__ __forceinline__ void cp_commit() { asm volatile("cp.async.commit_group;" ::: "memory"); }
__device__ __forceinline__ void cp_wait1()  { asm volatile("cp.async.wait_group 1;" ::: "memory"); }

__device__ __forceinline__ void ldm_x4(uint32_t* r, uint32_t addr) {
    asm volatile("ldmatrix.sync.aligned.m8n8.x4.shared.b16 {%0,%1,%2,%3}, [%4];"
                 : "=r"(r[0]), "=r"(r[1]), "=r"(r[2]), "=r"(r[3]) : "r"(addr));
}
__device__ __forceinline__ void mma16816(float* c, const uint32_t* a, const uint32_t* b) {
    asm volatile(
        "mma.sync.aligned.m16n8k16.row.col.f32.bf16.bf16.f32 "
        "{%0,%1,%2,%3}, {%4,%5,%6,%7}, {%8,%9}, {%0,%1,%2,%3};"
        : "+f"(c[0]), "+f"(c[1]), "+f"(c[2]), "+f"(c[3])
        : "r"(a[0]), "r"(a[1]), "r"(a[2]), "r"(a[3]), "r"(b[0]), "r"(b[1]));
}
__device__ __forceinline__ uint32_t pack_bf16x2(float a, float b) {
    __nv_bfloat16 ha = __float2bfloat16(a), hb = __float2bfloat16(b);
    return ((uint32_t)__bfloat16_as_ushort(hb) << 16) | (uint32_t)__bfloat16_as_ushort(ha);
}

// ---------------- reductions ----------------
__device__ __forceinline__ float warp_sum(float v) {
    #pragma unroll
    for (int o = 16; o > 0; o >>= 1) v += __shfl_xor_sync(0xffffffffu, v, o);
    return v;
}
__device__ __forceinline__ float warp_max(float v) {
    #pragma unroll
    for (int o = 16; o > 0; o >>= 1) v = fmaxf(v, __shfl_xor_sync(0xffffffffu, v, o));
    return v;
}
__device__ __forceinline__ float block_sum(float v, float* sm) {
    int wid = threadIdx.x >> 5, lid = threadIdx.x & 31;
    v = warp_sum(v);
    if (lid == 0) sm[wid] = v;
    __syncthreads();
    float r = (lid < 8) ? sm[lid] : 0.0f;
    r = warp_sum(r);
    r = __shfl_sync(0xffffffffu, r, 0);
    __syncthreads();
    return r;
}
__device__ __forceinline__ float block_max(float v, float* sm) {
    int wid = threadIdx.x >> 5, lid = threadIdx.x & 31;
    v = warp_max(v);
    if (lid == 0) sm[wid] = v;
    __syncthreads();
    float r = (lid < 8) ? sm[lid] : -INFINITY;
    r = warp_max(r);
    r = __shfl_sync(0xffffffffu, r, 0);
    __syncthreads();
    return r;
}

// ---------------- LN writing split planes ----------------
__global__ void ln_split_kernel(const float* __restrict__ x,
                                const float* __restrict__ gamma,
                                const float* __restrict__ beta,
                                __nv_bfloat16* __restrict__ hi,
                                __nv_bfloat16* __restrict__ lo) {
    __shared__ float sm[8];
    size_t row = blockIdx.x;
    const float* xr = x + row * Dz;
    int t = threadIdx.x;
    float v[4];
    float s = 0.f, s2 = 0.f;
    #pragma unroll
    for (int i = 0; i < 4; i++) {
        float val = xr[t + i * 256];
        v[i] = val; s += val; s2 += val * val;
    }
    float tot  = block_sum(s,  sm);
    float tot2 = block_sum(s2, sm);
    float mean = tot * (1.0f / Dz);
    float var  = tot2 * (1.0f / Dz) - mean * mean;
    float inv  = rsqrtf(var + 1e-5f);
    #pragma unroll
    for (int i = 0; i < 4; i++) {
        int c = t + i * 256;
        float y = gamma[c] * ((v[i] - mean) * inv) + beta[c];
        __nv_bfloat16 h = __float2bfloat16(y);
        hi[row * Dz + c] = h;
        lo[row * Dz + c] = __float2bfloat16(y - __bfloat162float(h));
    }
}

// ---------------- transpose + split: in fp32 [R,C] -> planes [C,R] ----------------
__global__ void transpose_split_kernel(const float* __restrict__ in,
                                       __nv_bfloat16* __restrict__ hi,
                                       __nv_bfloat16* __restrict__ lo,
                                       int R, int C, long sIn, long sOut) {
    __shared__ float t[32][33];
    in += (size_t)blockIdx.z * sIn;
    hi += (size_t)blockIdx.z * sOut;
    lo += (size_t)blockIdx.z * sOut;
    int rb = blockIdx.y * 32, cb = blockIdx.x * 32;
    int tx = threadIdx.x, ty = threadIdx.y;
    #pragma unroll
    for (int k = 0; k < 4; k++)
        t[ty + 8 * k][tx] = in[(size_t)(rb + ty + 8 * k) * C + cb + tx];
    __syncthreads();
    #pragma unroll
    for (int k = 0; k < 4; k++) {
        float v = t[tx][ty + 8 * k];
        int orow = cb + ty + 8 * k, ocol = rb + tx;
        __nv_bfloat16 h = __float2bfloat16(v);
        hi[(size_t)orow * R + ocol] = h;
        lo[(size_t)orow * R + ocol] = __float2bfloat16(v - __bfloat162float(h));
    }
}

// ---------------- causal softmax -> split probs (masked-chunk load skip) ----------------
__global__ void softmax_split_kernel(const float* __restrict__ sc,
                                     __nv_bfloat16* __restrict__ Phi,
                                     __nv_bfloat16* __restrict__ Plo) {
    __shared__ float sm[8];
    int row = blockIdx.x;
    int r = row & (Sz - 1);
    const float* src = sc + (size_t)row * Sz;
    int t = threadIdx.x;
    float v[8];
    float m = -INFINITY;
    #pragma unroll
    for (int i = 0; i < 8; i++) {
        int c = t + i * 256;
        float val = -INFINITY;
        if (i * 256 <= r) {               // chunk has at least one unmasked col
            val = src[c];
            val = (c <= r) ? val : -INFINITY;
        }
        v[i] = val;
        m = fmaxf(m, val);
    }
    m = block_max(m, sm);
    float s = 0.f;
    #pragma unroll
    for (int i = 0; i < 8; i++) {
        v[i] = expf(v[i] - m);
        s += v[i];
    }
    s = block_sum(s, sm);
    float inv = 1.0f / s;
    #pragma unroll
    for (int i = 0; i < 8; i++) {
        int c = t + i * 256;
        float p = v[i] * inv;
        __nv_bfloat16 h = __float2bfloat16(p);
        Phi[(size_t)row * Sz + c] = h;
        Plo[(size_t)row * Sz + c] = __float2bfloat16(p - __bfloat162float(h));
    }
}

// ---------------- split-bf16 GEMM via mma.sync (HMMA) ----------------
// C[M,N] = alpha * sum_k A[m,k]*Bt[n,k]  (A,Bt as hi/lo bf16 planes, K-major)
// OUTM: 0 = fp32 C, 1 = split planes (Chi/Clo)
// Term-major MMA ordering: same-accumulator reuse distance 4 (was 1).
template<int OUTM, bool BIAS_, bool RELU_, bool RES_, bool CAUSAL_, bool KTRIM_>
__global__ void __launch_bounds__(256, 2)
tc_gemm(const __nv_bfloat16* __restrict__ Ahi, const __nv_bfloat16* __restrict__ Alo,
        const __nv_bfloat16* __restrict__ Bhi, const __nv_bfloat16* __restrict__ Blo,
        float* __restrict__ Cf,
        __nv_bfloat16* __restrict__ Chi, __nv_bfloat16* __restrict__ Clo,
        const float* __restrict__ bias, const float* __restrict__ res,
        int M, int N, int K, float alpha, long sA, long sB, long sC)
{
    extern __shared__ char dynsmem[];
    const int bm = blockIdx.y * BM;
    const int bn = blockIdx.x * BN;
    if (CAUSAL_ && bn >= bm + BM) return;   // fully masked tile (softmax re-masks)

    const int tid  = threadIdx.x;
    const int wid  = tid >> 5;
    const int lane = tid & 31;
    const int warp_m = wid >> 1;     // 0..3  (rows, 32 each)
    const int warp_n = wid & 1;      // 0..1  (cols, 64 each)

    Ahi += (size_t)blockIdx.z * sA;  Alo += (size_t)blockIdx.z * sA;
    Bhi += (size_t)blockIdx.z * sB;  Blo += (size_t)blockIdx.z * sB;
    if (OUTM == 0) Cf += (size_t)blockIdx.z * sC;
    else { Chi += (size_t)blockIdx.z * sC; Clo += (size_t)blockIdx.z * sC; }
    if (RES_) res += (size_t)blockIdx.z * sC;

    const uint32_t smem_base = smem_u32(dynsmem);

    const int kmax = KTRIM_ ? min(K, bm + BM) : K;
    const int nst  = kmax >> 5;      // BK=32

    // per-stage cp.async: 2048 chunks of 16B (A h/l + B h/l), 8 per thread
    auto issue_loads = [&](int s) {
        uint32_t sb = smem_base + (uint32_t)(s & 1) * STAGE_BYTES;
        int kt = s * BK;
        #pragma unroll
        for (int i = 0; i < 4; i++) {            // A: 1024 chunks
            int id = i * 256 + tid;              // 0..1023
            const __nv_bfloat16* src = (id < 512) ? Ahi : Alo;
            uint32_t off = (id < 512) ? 0u : TILE_BYTES;
            int r  = (id >> 2) & 127;
            int c4 = id & 3;
            cp16(sb + off + (uint32_t)(r * TSTRIDE + c4 * 8) * 2,
                 src + (size_t)(bm + r) * K + kt + c4 * 8);
        }
        #pragma unroll
        for (int i = 0; i < 4; i++) {            // B: 1024 chunks
            int id = i * 256 + tid;
            const __nv_bfloat16* src = (id < 512) ? Bhi : Blo;
            uint32_t off = 2u * TILE_BYTES + ((id < 512) ? 0u : TILE_BYTES);
            int r  = (id >> 2) & 127;
            int c4 = id & 3;
            cp16(sb + off + (uint32_t)(r * TSTRIDE + c4 * 8) * 2,
                 src + (size_t)(bn + r) * K + kt + c4 * 8);
        }
    };

    float acc[2][8][4];
    #pragma unroll
    for (int i = 0; i < 2; i++)
        #pragma unroll
        for (int j = 0; j < 8; j++)
            #pragma unroll
            for (int k = 0; k < 4; k++) acc[i][j][k] = 0.f;

    issue_loads(0); cp_commit();
    if (nst > 1) issue_loads(1);
    cp_commit();

    for (int s = 0; s < nst; s++) {
        cp_wait1();
        __syncthreads();

        uint32_t sb = smem_base + (uint32_t)(s & 1) * STAGE_BYTES;
        uint32_t aH = sb, aL = sb + TILE_BYTES;
        uint32_t bH = sb + 2u * TILE_BYTES, bL = sb + 3u * TILE_BYTES;

        #pragma unroll
        for (int k16 = 0; k16 < BK; k16 += 16) {
            // A fragments: 2 m16 chunks x {hi,lo}
            uint32_t ah[2][4], al[2][4];
            #pragma unroll
            for (int mi = 0; mi < 2; mi++) {
                uint32_t arow = (uint32_t)(warp_m * 32 + mi * 16 + (lane & 15));
                uint32_t aoff = (arow * TSTRIDE + (uint32_t)(k16 + (lane >> 4) * 8)) * 2;
                ldm_x4(ah[mi], aH + aoff);
                ldm_x4(al[mi], aL + aoff);
            }
            // B: 4 n16 chunks; term-major MMA issue within each chunk
            #pragma unroll
            for (int j = 0; j < 4; j++) {
                uint32_t brow = (uint32_t)(warp_n * 64 + j * 16 + ((lane >> 4) * 8) + (lane & 7));
                uint32_t boff = (brow * TSTRIDE + (uint32_t)(k16 + ((lane >> 3) & 1) * 8)) * 2;
                uint32_t bh[4], bl[4];
                ldm_x4(bh, bH + boff);
                ldm_x4(bl, bL + boff);
                // term hh: 4 independent accumulators
                #pragma unroll
                for (int mi = 0; mi < 2; mi++)
                    #pragma unroll
                    for (int sub = 0; sub < 2; sub++)
                        mma16816(acc[mi][j * 2 + sub], ah[mi], bh + sub * 2);
                // term hl
                #pragma unroll
                for (int mi = 0; mi < 2; mi++)
                    #pragma unroll
                    for (int sub = 0; sub < 2; sub++)
                        mma16816(acc[mi][j * 2 + sub], ah[mi], bl + sub * 2);
                // term lh
                #pragma unroll
                for (int mi = 0; mi < 2; mi++)
                    #pragma unroll
                    for (int sub = 0; sub < 2; sub++)
                        mma16816(acc[mi][j * 2 + sub], al[mi], bh + sub * 2);
            }
        }
        __syncthreads();
        if (s + 2 < nst) issue_loads(s + 2);
        cp_commit();
    }

    // ---------------- epilogue from register accumulators ----------------
    const int g = lane >> 2, t4 = lane & 3;
    #pragma unroll
    for (int mi = 0; mi < 2; mi++) {
        #pragma unroll
        for (int ni = 0; ni < 8; ni++) {
            int col = bn + warp_n * 64 + ni * 8 + t4 * 2;
            #pragma unroll
            for (int half = 0; half < 2; half++) {
                int row = bm + warp_m * 32 + mi * 16 + g + half * 8;
                float v0 = acc[mi][ni][half * 2 + 0] * alpha;
                float v1 = acc[mi][ni][half * 2 + 1] * alpha;
                if (BIAS_) { v0 += bias[col]; v1 += bias[col + 1]; }
                if (RELU_) { v0 = fmaxf(v0, 0.f); v1 = fmaxf(v1, 0.f); }
                if (RES_) {
                    float2 rv = *(const float2*)(res + (size_t)row * N + col);
                    v0 += rv.x; v1 += rv.y;
                }
                if (OUTM == 0) {
                    float2 o; o.x = v0; o.y = v1;
                    *(float2*)(Cf + (size_t)row * N + col) = o;
                } else {
                    uint32_t hp = pack_bf16x2(v0, v1);
                    float l0 = v0 - __bfloat162float(__float2bfloat16(v0));
                    float l1 = v1 - __bfloat162float(__float2bfloat16(v1));
                    uint32_t lp = pack_bf16x2(l0, l1);
                    *(uint32_t*)(Chi + (size_t)row * N + col) = hp;
                    *(uint32_t*)(Clo + (size_t)row * N + col) = lp;
                }
            }
        }
    }
}

// ---------------- launcher ----------------
extern "C" void kernel_launch(void* const* d_in, const int* in_sizes, int n_in,
                              void* d_out, int out_size) {
    (void)in_sizes; (void)n_in; (void)out_size;
    const float* x      = (const float*)d_in[0];
    const float* Qw     = (const float*)d_in[1];
    const float* Kw     = (const float*)d_in[2];
    const float* Vw     = (const float*)d_in[3];
    const float* w1     = (const float*)d_in[4];
    const float* b1     = (const float*)d_in[5];
    const float* w2     = (const float*)d_in[6];
    const float* b2     = (const float*)d_in[7];
    const float* gamma1 = (const float*)d_in[8];
    const float* beta1  = (const float*)d_in[9];
    const float* gamma2 = (const float*)d_in[10];
    const float* beta2  = (const float*)d_in[11];
    float* out = (float*)d_out;

    __nv_bfloat16 *ln1h,*ln1l,*qwTh,*qwTl,*kwTh,*kwTl,*vwTh,*vwTl;
    __nv_bfloat16 *qh,*ql,*kh,*kl,*vTh,*vTl,*ph,*pl,*ln2h,*ln2l;
    __nv_bfloat16 *w1Th,*w1Tl,*w2Th,*w2Tl,*hh,*hl;
    float *vf,*sc,*x1;
    cudaGetSymbolAddress((void**)&ln1h, s_ln1h); cudaGetSymbolAddress((void**)&ln1l, s_ln1l);
    cudaGetSymbolAddress((void**)&qwTh, s_qwTh); cudaGetSymbolAddress((void**)&qwTl, s_qwTl);
    cudaGetSymbolAddress((void**)&kwTh, s_kwTh); cudaGetSymbolAddress((void**)&kwTl, s_kwTl);
    cudaGetSymbolAddress((void**)&vwTh, s_vwTh); cudaGetSymbolAddress((void**)&vwTl, s_vwTl);
    cudaGetSymbolAddress((void**)&qh, s_qh);     cudaGetSymbolAddress((void**)&ql, s_ql);
    cudaGetSymbolAddress((void**)&kh, s_kh);     cudaGetSymbolAddress((void**)&kl, s_kl);
    cudaGetSymbolAddress((void**)&vf, s_v);
    cudaGetSymbolAddress((void**)&vTh, s_vTh);   cudaGetSymbolAddress((void**)&vTl, s_vTl);
    cudaGetSymbolAddress((void**)&sc, s_sc);
    cudaGetSymbolAddress((void**)&ph, s_ph);     cudaGetSymbolAddress((void**)&pl, s_pl);
    cudaGetSymbolAddress((void**)&x1, s_x1);
    cudaGetSymbolAddress((void**)&ln2h, s_ln2h); cudaGetSymbolAddress((void**)&ln2l, s_ln2l);
    cudaGetSymbolAddress((void**)&w1Th, s_w1Th); cudaGetSymbolAddress((void**)&w1Tl, s_w1Tl);
    cudaGetSymbolAddress((void**)&w2Th, s_w2Th); cudaGetSymbolAddress((void**)&w2Tl, s_w2Tl);
    cudaGetSymbolAddress((void**)&hh, s_hh);     cudaGetSymbolAddress((void**)&hl, s_hl);

    cudaFuncSetAttribute(tc_gemm<1,false,false,false,false,false>, cudaFuncAttributeMaxDynamicSharedMemorySize, SMEM_TOTAL);
    cudaFuncSetAttribute(tc_gemm<0,false,false,false,false,false>, cudaFuncAttributeMaxDynamicSharedMemorySize, SMEM_TOTAL);
    cudaFuncSetAttribute(tc_gemm<0,false,false,false,true ,false>, cudaFuncAttributeMaxDynamicSharedMemorySize, SMEM_TOTAL);
    cudaFuncSetAttribute(tc_gemm<0,false,false,true ,false,true >, cudaFuncAttributeMaxDynamicSharedMemorySize, SMEM_TOTAL);
    cudaFuncSetAttribute(tc_gemm<1,true ,true ,false,false,false>, cudaFuncAttributeMaxDynamicSharedMemorySize, SMEM_TOTAL);
    cudaFuncSetAttribute(tc_gemm<0,true ,false,true ,false,false>, cudaFuncAttributeMaxDynamicSharedMemorySize, SMEM_TOTAL);

    const float scale = 1.0f / 32.0f;

    // 1) LN1 -> split planes
    ln_split_kernel<<<BSz, 256>>>(x, gamma1, beta1, ln1h, ln1l);

    // 2) weight transposes -> split planes
    {
        dim3 blk(32, 8);
        transpose_split_kernel<<<dim3(Dz/32, Dz/32, 1), blk>>>(Qw, qwTh, qwTl, Dz, Dz, 0, 0);
        transpose_split_kernel<<<dim3(Dz/32, Dz/32, 1), blk>>>(Kw, kwTh, kwTl, Dz, Dz, 0, 0);
        transpose_split_kernel<<<dim3(Dz/32, Dz/32, 1), blk>>>(Vw, vwTh, vwTl, Dz, Dz, 0, 0);
        transpose_split_kernel<<<dim3(Fz/32, Dz/32, 1), blk>>>(w1, w1Th, w1Tl, Dz, Fz, 0, 0);
        transpose_split_kernel<<<dim3(Dz/32, Fz/32, 1), blk>>>(w2, w2Th, w2Tl, Fz, Dz, 0, 0);
    }

    // 3) Q, K projections -> split planes; V -> fp32
    {
        dim3 grid(Dz/BN, BSz/BM, 1);
        tc_gemm<1,false,false,false,false,false><<<grid, 256, SMEM_TOTAL>>>(
            ln1h, ln1l, qwTh, qwTl, nullptr, qh, ql, nullptr, nullptr,
            BSz, Dz, Dz, 1.f, 0, 0, 0);
        tc_gemm<1,false,false,false,false,false><<<grid, 256, SMEM_TOTAL>>>(
            ln1h, ln1l, kwTh, kwTl, nullptr, kh, kl, nullptr, nullptr,
            BSz, Dz, Dz, 1.f, 0, 0, 0);
        tc_gemm<0,false,false,false,false,false><<<grid, 256, SMEM_TOTAL>>>(
            ln1h, ln1l, vwTh, vwTl, vf, nullptr, nullptr, nullptr, nullptr,
            BSz, Dz, Dz, 1.f, 0, 0, 0);
    }

    // 4) V^T split planes (per batch [D,S])
    {
        dim3 blk(32, 8);
        transpose_split_kernel<<<dim3(Dz/32, Sz/32, Bz), blk>>>(
            vf, vTh, vTl, Sz, Dz, (long)Sz*Dz, (long)Dz*Sz);
    }

    // 5) scores = Q@K^T * scale (causal tile-skip), fp32 out
    {
        dim3 grid(Sz/BN, Sz/BM, Bz);
        tc_gemm<0,false,false,false,true,false><<<grid, 256, SMEM_TOTAL>>>(
            qh, ql, kh, kl, sc, nullptr, nullptr, nullptr, nullptr,
            Sz, Sz, Dz, scale, (long)Sz*Dz, (long)Sz*Dz, (long)Sz*Sz);
    }

    // 6) causal softmax -> split probs
    softmax_split_kernel<<<BSz, 256>>>(sc, ph, pl);

    // 7) x1 = x + P@V   (K trimmed by causality)
    {
        dim3 grid(Dz/BN, Sz/BM, Bz);
        tc_gemm<0,false,false,true,false,true><<<grid, 256, SMEM_TOTAL>>>(
            ph, pl, vTh, vTl, x1, nullptr, nullptr, nullptr, x,
            Sz, Dz, Sz, 1.f, (long)Sz*Sz, (long)Dz*Sz, (long)Sz*Dz);
    }

    // 8) LN2 -> split planes
    ln_split_kernel<<<BSz, 256>>>(x1, gamma2, beta2, ln2h, ln2l);

    // 9) h = relu(ln2 @ w1 + b1) -> split planes
    {
        dim3 grid(Fz/BN, BSz/BM, 1);
        tc_gemm<1,true,true,false,false,false><<<grid, 256, SMEM_TOTAL>>>(
            ln2h, ln2l, w1Th, w1Tl, nullptr, hh, hl, b1, nullptr,
            BSz, Fz, Dz, 1.f, 0, 0, 0);
    }

    // 10) out = x1 + h @ w2 + b2
    {
        dim3 grid(Dz/BN, BSz/BM, 1);
        tc_gemm<0,true,false,true,false,false><<<grid, 256, SMEM_TOTAL>>>(
            hh, hl, w2Th, w2Tl, out, nullptr, nullptr, b2, x1,
            BSz, Dz, Fz, 1.f, 0, 0, 0);
    }
}

// round 8
// speedup vs baseline: 2.6139x; 2.5658x over previous
#include <cuda_runtime.h>
#include <cuda_fp16.h>
#include <math.h>
#include <stdint.h>

// Problem constants
#define Bz 4
#define Sz 2048
#define Dz 1024
#define Fz 4096
#define BSz (Bz*Sz)   // 8192

// GEMM tiling (mma.sync fp16 path)
#define BM 128
#define BN 128
#define BK 32
#define TSTRIDE 40                    // padded row stride in fp16 elems (80B)
#define TILE_BYTES (128*TSTRIDE*2)    // 10240 B per operand tile
#define STAGE_BYTES (2*TILE_BYTES)    // A, B
#define SMEM_TOTAL (2*STAGE_BYTES)    // 40960 B (2 stages)

// ---------------- scratch (static device globals; no allocation) ----------------
#define AL __align__(256)
__device__ AL __half s_ln1[(size_t)BSz*Dz];
__device__ AL __half s_qwT[(size_t)Dz*Dz];
__device__ AL __half s_kwT[(size_t)Dz*Dz];
__device__ AL __half s_vwT[(size_t)Dz*Dz];
__device__ AL __half s_q  [(size_t)BSz*Dz];
__device__ AL __half s_k  [(size_t)BSz*Dz];
__device__ AL float  s_v  [(size_t)BSz*Dz];
__device__ AL __half s_vT [(size_t)Bz*Dz*Sz];
__device__ AL float  s_sc [(size_t)Bz*Sz*Sz];
__device__ AL __half s_p  [(size_t)Bz*Sz*Sz];
__device__ AL float  s_x1 [(size_t)BSz*Dz];
__device__ AL __half s_ln2[(size_t)BSz*Dz];
__device__ AL __half s_w1T[(size_t)Fz*Dz];
__device__ AL __half s_w2T[(size_t)Dz*Fz];
__device__ AL __half s_h  [(size_t)BSz*Fz];

// ---------------- PTX helpers ----------------
__device__ __forceinline__ uint32_t smem_u32(const void* p) {
    uint32_t a;
    asm("{ .reg .u64 t; cvta.to.shared.u64 t, %1; cvt.u32.u64 %0, t; }" : "=r"(a) : "l"(p));
    return a;
}
__device__ __forceinline__ void cp16(uint32_t dst, const void* src) {
    asm volatile("cp.async.cg.shared.global [%0], [%1], 16;" :: "r"(dst), "l"(src));
}
__device__ __forceinline__ void cp_commit() { asm volatile("cp.async.commit_group;" ::: "memory"); }
__device__ __forceinline__ void cp_wait1()  { asm volatile("cp.async.wait_group 1;" ::: "memory"); }

__device__ __forceinline__ void ldm_x4(uint32_t* r, uint32_t addr) {
    asm volatile("ldmatrix.sync.aligned.m8n8.x4.shared.b16 {%0,%1,%2,%3}, [%4];"
                 : "=r"(r[0]), "=r"(r[1]), "=r"(r[2]), "=r"(r[3]) : "r"(addr));
}
__device__ __forceinline__ void mma16816(float* c, const uint32_t* a, const uint32_t* b) {
    asm volatile(
        "mma.sync.aligned.m16n8k16.row.col.f32.f16.f16.f32 "
        "{%0,%1,%2,%3}, {%4,%5,%6,%7}, {%8,%9}, {%0,%1,%2,%3};"
        : "+f"(c[0]), "+f"(c[1]), "+f"(c[2]), "+f"(c[3])
        : "r"(a[0]), "r"(a[1]), "r"(a[2]), "r"(a[3]), "r"(b[0]), "r"(b[1]));
}
__device__ __forceinline__ uint32_t pack_half2(float a, float b) {
    __half2 h = __floats2half2_rn(a, b);
    return *(uint32_t*)&h;
}

// ---------------- reductions ----------------
__device__ __forceinline__ float warp_sum(float v) {
    #pragma unroll
    for (int o = 16; o > 0; o >>= 1) v += __shfl_xor_sync(0xffffffffu, v, o);
    return v;
}
__device__ __forceinline__ float warp_max(float v) {
    #pragma unroll
    for (int o = 16; o > 0; o >>= 1) v = fmaxf(v, __shfl_xor_sync(0xffffffffu, v, o));
    return v;
}
__device__ __forceinline__ float block_sum(float v, float* sm) {
    int wid = threadIdx.x >> 5, lid = threadIdx.x & 31;
    v = warp_sum(v);
    if (lid == 0) sm[wid] = v;
    __syncthreads();
    float r = (lid < 8) ? sm[lid] : 0.0f;
    r = warp_sum(r);
    r = __shfl_sync(0xffffffffu, r, 0);
    __syncthreads();
    return r;
}
__device__ __forceinline__ float block_max(float v, float* sm) {
    int wid = threadIdx.x >> 5, lid = threadIdx.x & 31;
    v = warp_max(v);
    if (lid == 0) sm[wid] = v;
    __syncthreads();
    float r = (lid < 8) ? sm[lid] : -INFINITY;
    r = warp_max(r);
    r = __shfl_sync(0xffffffffu, r, 0);
    __syncthreads();
    return r;
}

// ---------------- LN -> fp16 ----------------
__global__ void ln_half_kernel(const float* __restrict__ x,
                               const float* __restrict__ gamma,
                               const float* __restrict__ beta,
                               __half* __restrict__ out) {
    __shared__ float sm[8];
    size_t row = blockIdx.x;
    const float* xr = x + row * Dz;
    int t = threadIdx.x;
    float v[4];
    float s = 0.f, s2 = 0.f;
    #pragma unroll
    for (int i = 0; i < 4; i++) {
        float val = xr[t + i * 256];
        v[i] = val; s += val; s2 += val * val;
    }
    float tot  = block_sum(s,  sm);
    float tot2 = block_sum(s2, sm);
    float mean = tot * (1.0f / Dz);
    float var  = tot2 * (1.0f / Dz) - mean * mean;
    float inv  = rsqrtf(var + 1e-5f);
    #pragma unroll
    for (int i = 0; i < 4; i++) {
        int c = t + i * 256;
        float y = gamma[c] * ((v[i] - mean) * inv) + beta[c];
        out[row * Dz + c] = __float2half(y);
    }
}

// ---------------- transpose: fp32 [R,C] -> fp16 [C,R] ----------------
__global__ void transpose_half_kernel(const float* __restrict__ in,
                                      __half* __restrict__ out,
                                      int R, int C, long sIn, long sOut) {
    __shared__ float t[32][33];
    in  += (size_t)blockIdx.z * sIn;
    out += (size_t)blockIdx.z * sOut;
    int rb = blockIdx.y * 32, cb = blockIdx.x * 32;
    int tx = threadIdx.x, ty = threadIdx.y;
    #pragma unroll
    for (int k = 0; k < 4; k++)
        t[ty + 8 * k][tx] = in[(size_t)(rb + ty + 8 * k) * C + cb + tx];
    __syncthreads();
    #pragma unroll
    for (int k = 0; k < 4; k++) {
        float v = t[tx][ty + 8 * k];
        int orow = cb + ty + 8 * k, ocol = rb + tx;
        out[(size_t)orow * R + ocol] = __float2half(v);
    }
}

// ---------------- causal softmax -> fp16 probs (masked-chunk load skip) ----------------
__global__ void softmax_half_kernel(const float* __restrict__ sc,
                                    __half* __restrict__ P) {
    __shared__ float sm[8];
    int row = blockIdx.x;
    int r = row & (Sz - 1);
    const float* src = sc + (size_t)row * Sz;
    int t = threadIdx.x;
    float v[8];
    float m = -INFINITY;
    #pragma unroll
    for (int i = 0; i < 8; i++) {
        int c = t + i * 256;
        float val = -INFINITY;
        if (i * 256 <= r) {
            val = src[c];
            val = (c <= r) ? val : -INFINITY;
        }
        v[i] = val;
        m = fmaxf(m, val);
    }
    m = block_max(m, sm);
    float s = 0.f;
    #pragma unroll
    for (int i = 0; i < 8; i++) {
        v[i] = expf(v[i] - m);
        s += v[i];
    }
    s = block_sum(s, sm);
    float inv = 1.0f / s;
    #pragma unroll
    for (int i = 0; i < 8; i++) {
        int c = t + i * 256;
        P[(size_t)row * Sz + c] = __float2half(v[i] * inv);
    }
}

// ---------------- fp16 GEMM via mma.sync (HMMA) ----------------
// C[M,N] = alpha * sum_k A[m,k]*Bt[n,k]  (A,Bt fp16, K-major)
// OUTM: 0 = fp32 C, 1 = fp16 C
template<int OUTM, bool BIAS_, bool RELU_, bool RES_, bool CAUSAL_, bool KTRIM_>
__global__ void __launch_bounds__(256, 2)
hgemm(const __half* __restrict__ A, const __half* __restrict__ B,
      float* __restrict__ Cf, __half* __restrict__ Ch,
      const float* __restrict__ bias, const float* __restrict__ res,
      int M, int N, int K, float alpha, long sA, long sB, long sC)
{
    extern __shared__ char dynsmem[];
    const int bm = blockIdx.y * BM;
    const int bn = blockIdx.x * BN;
    if (CAUSAL_ && bn >= bm + BM) return;   // fully masked tile (softmax re-masks)

    const int tid  = threadIdx.x;
    const int wid  = tid >> 5;
    const int lane = tid & 31;
    const int warp_m = wid >> 1;     // 0..3  (rows, 32 each)
    const int warp_n = wid & 1;      // 0..1  (cols, 64 each)

    A += (size_t)blockIdx.z * sA;
    B += (size_t)blockIdx.z * sB;
    if (OUTM == 0) Cf += (size_t)blockIdx.z * sC;
    else           Ch += (size_t)blockIdx.z * sC;
    if (RES_) res += (size_t)blockIdx.z * sC;

    const uint32_t smem_base = smem_u32(dynsmem);

    const int kmax = KTRIM_ ? min(K, bm + BM) : K;
    const int nst  = kmax >> 5;      // BK=32

    // per-stage cp.async: A 512 + B 512 chunks of 16B, 4 per thread
    auto issue_loads = [&](int s) {
        uint32_t sb = smem_base + (uint32_t)(s & 1) * STAGE_BYTES;
        int kt = s * BK;
        #pragma unroll
        for (int i = 0; i < 2; i++) {            // A: 512 chunks
            int id = i * 256 + tid;              // 0..511
            int r  = id >> 2;                    // 0..127
            int c4 = id & 3;
            cp16(sb + (uint32_t)(r * TSTRIDE + c4 * 8) * 2,
                 A + (size_t)(bm + r) * K + kt + c4 * 8);
        }
        #pragma unroll
        for (int i = 0; i < 2; i++) {            // B: 512 chunks
            int id = i * 256 + tid;
            int r  = id >> 2;
            int c4 = id & 3;
            cp16(sb + TILE_BYTES + (uint32_t)(r * TSTRIDE + c4 * 8) * 2,
                 B + (size_t)(bn + r) * K + kt + c4 * 8);
        }
    };

    float acc[2][8][4];
    #pragma unroll
    for (int i = 0; i < 2; i++)
        #pragma unroll
        for (int j = 0; j < 8; j++)
            #pragma unroll
            for (int k = 0; k < 4; k++) acc[i][j][k] = 0.f;

    issue_loads(0); cp_commit();
    if (nst > 1) issue_loads(1);
    cp_commit();

    for (int s = 0; s < nst; s++) {
        cp_wait1();
        __syncthreads();

        uint32_t sb = smem_base + (uint32_t)(s & 1) * STAGE_BYTES;
        uint32_t aT = sb, bT = sb + TILE_BYTES;

        #pragma unroll
        for (int k16 = 0; k16 < BK; k16 += 16) {
            uint32_t af[2][4];
            #pragma unroll
            for (int mi = 0; mi < 2; mi++) {
                uint32_t arow = (uint32_t)(warp_m * 32 + mi * 16 + (lane & 15));
                uint32_t aoff = (arow * TSTRIDE + (uint32_t)(k16 + (lane >> 4) * 8)) * 2;
                ldm_x4(af[mi], aT + aoff);
            }
            #pragma unroll
            for (int j = 0; j < 4; j++) {
                uint32_t brow = (uint32_t)(warp_n * 64 + j * 16 + ((lane >> 4) * 8) + (lane & 7));
                uint32_t boff = (brow * TSTRIDE + (uint32_t)(k16 + ((lane >> 3) & 1) * 8)) * 2;
                uint32_t bf[4];
                ldm_x4(bf, bT + boff);
                #pragma unroll
                for (int mi = 0; mi < 2; mi++)
                    #pragma unroll
                    for (int sub = 0; sub < 2; sub++)
                        mma16816(acc[mi][j * 2 + sub], af[mi], bf + sub * 2);
            }
        }
        __syncthreads();
        if (s + 2 < nst) issue_loads(s + 2);
        cp_commit();
    }

    // ---------------- epilogue from register accumulators ----------------
    const int g = lane >> 2, t4 = lane & 3;
    #pragma unroll
    for (int mi = 0; mi < 2; mi++) {
        #pragma unroll
        for (int ni = 0; ni < 8; ni++) {
            int col = bn + warp_n * 64 + ni * 8 + t4 * 2;
            #pragma unroll
            for (int half = 0; half < 2; half++) {
                int row = bm + warp_m * 32 + mi * 16 + g + half * 8;
                float v0 = acc[mi][ni][half * 2 + 0] * alpha;
                float v1 = acc[mi][ni][half * 2 + 1] * alpha;
                if (BIAS_) { v0 += bias[col]; v1 += bias[col + 1]; }
                if (RELU_) { v0 = fmaxf(v0, 0.f); v1 = fmaxf(v1, 0.f); }
                if (RES_) {
                    float2 rv = *(const float2*)(res + (size_t)row * N + col);
                    v0 += rv.x; v1 += rv.y;
                }
                if (OUTM == 0) {
                    float2 o; o.x = v0; o.y = v1;
                    *(float2*)(Cf + (size_t)row * N + col) = o;
                } else {
                    *(uint32_t*)(Ch + (size_t)row * N + col) = pack_half2(v0, v1);
                }
            }
        }
    }
}

// ---------------- launcher ----------------
extern "C" void kernel_launch(void* const* d_in, const int* in_sizes, int n_in,
                              void* d_out, int out_size) {
    (void)in_sizes; (void)n_in; (void)out_size;
    const float* x      = (const float*)d_in[0];
    const float* Qw     = (const float*)d_in[1];
    const float* Kw     = (const float*)d_in[2];
    const float* Vw     = (const float*)d_in[3];
    const float* w1     = (const float*)d_in[4];
    const float* b1     = (const float*)d_in[5];
    const float* w2     = (const float*)d_in[6];
    const float* b2     = (const float*)d_in[7];
    const float* gamma1 = (const float*)d_in[8];
    const float* beta1  = (const float*)d_in[9];
    const float* gamma2 = (const float*)d_in[10];
    const float* beta2  = (const float*)d_in[11];
    float* out = (float*)d_out;

    __half *ln1,*qwT,*kwT,*vwT,*q,*k,*vT,*p,*ln2,*w1T,*w2T,*h;
    float *vf,*sc,*x1;
    cudaGetSymbolAddress((void**)&ln1, s_ln1);
    cudaGetSymbolAddress((void**)&qwT, s_qwT);
    cudaGetSymbolAddress((void**)&kwT, s_kwT);
    cudaGetSymbolAddress((void**)&vwT, s_vwT);
    cudaGetSymbolAddress((void**)&q,   s_q);
    cudaGetSymbolAddress((void**)&k,   s_k);
    cudaGetSymbolAddress((void**)&vf,  s_v);
    cudaGetSymbolAddress((void**)&vT,  s_vT);
    cudaGetSymbolAddress((void**)&sc,  s_sc);
    cudaGetSymbolAddress((void**)&p,   s_p);
    cudaGetSymbolAddress((void**)&x1,  s_x1);
    cudaGetSymbolAddress((void**)&ln2, s_ln2);
    cudaGetSymbolAddress((void**)&w1T, s_w1T);
    cudaGetSymbolAddress((void**)&w2T, s_w2T);
    cudaGetSymbolAddress((void**)&h,   s_h);

    cudaFuncSetAttribute(hgemm<1,false,false,false,false,false>, cudaFuncAttributeMaxDynamicSharedMemorySize, SMEM_TOTAL);
    cudaFuncSetAttribute(hgemm<0,false,false,false,false,false>, cudaFuncAttributeMaxDynamicSharedMemorySize, SMEM_TOTAL);
    cudaFuncSetAttribute(hgemm<0,false,false,false,true ,false>, cudaFuncAttributeMaxDynamicSharedMemorySize, SMEM_TOTAL);
    cudaFuncSetAttribute(hgemm<0,false,false,true ,false,true >, cudaFuncAttributeMaxDynamicSharedMemorySize, SMEM_TOTAL);
    cudaFuncSetAttribute(hgemm<1,true ,true ,false,false,false>, cudaFuncAttributeMaxDynamicSharedMemorySize, SMEM_TOTAL);
    cudaFuncSetAttribute(hgemm<0,true ,false,true ,false,false>, cudaFuncAttributeMaxDynamicSharedMemorySize, SMEM_TOTAL);

    const float scale = 1.0f / 32.0f;

    // 1) LN1 -> fp16
    ln_half_kernel<<<BSz, 256>>>(x, gamma1, beta1, ln1);

    // 2) weight transposes -> fp16
    {
        dim3 blk(32, 8);
        transpose_half_kernel<<<dim3(Dz/32, Dz/32, 1), blk>>>(Qw, qwT, Dz, Dz, 0, 0);
        transpose_half_kernel<<<dim3(Dz/32, Dz/32, 1), blk>>>(Kw, kwT, Dz, Dz, 0, 0);
        transpose_half_kernel<<<dim3(Dz/32, Dz/32, 1), blk>>>(Vw, vwT, Dz, Dz, 0, 0);
        transpose_half_kernel<<<dim3(Fz/32, Dz/32, 1), blk>>>(w1, w1T, Dz, Fz, 0, 0);
        transpose_half_kernel<<<dim3(Dz/32, Fz/32, 1), blk>>>(w2, w2T, Fz, Dz, 0, 0);
    }

    // 3) Q, K projections -> fp16; V -> fp32
    {
        dim3 grid(Dz/BN, BSz/BM, 1);
        hgemm<1,false,false,false,false,false><<<grid, 256, SMEM_TOTAL>>>(
            ln1, qwT, nullptr, q, nullptr, nullptr, BSz, Dz, Dz, 1.f, 0, 0, 0);
        hgemm<1,false,false,false,false,false><<<grid, 256, SMEM_TOTAL>>>(
            ln1, kwT, nullptr, k, nullptr, nullptr, BSz, Dz, Dz, 1.f, 0, 0, 0);
        hgemm<0,false,false,false,false,false><<<grid, 256, SMEM_TOTAL>>>(
            ln1, vwT, vf, nullptr, nullptr, nullptr, BSz, Dz, Dz, 1.f, 0, 0, 0);
    }

    // 4) V^T -> fp16 (per batch [D,S])
    {
        dim3 blk(32, 8);
        transpose_half_kernel<<<dim3(Dz/32, Sz/32, Bz), blk>>>(
            vf, vT, Sz, Dz, (long)Sz*Dz, (long)Dz*Sz);
    }

    // 5) scores = Q@K^T * scale (causal tile-skip), fp32 out
    {
        dim3 grid(Sz/BN, Sz/BM, Bz);
        hgemm<0,false,false,false,true,false><<<grid, 256, SMEM_TOTAL>>>(
            q, k, sc, nullptr, nullptr, nullptr,
            Sz, Sz, Dz, scale, (long)Sz*Dz, (long)Sz*Dz, (long)Sz*Sz);
    }

    // 6) causal softmax -> fp16 probs
    softmax_half_kernel<<<BSz, 256>>>(sc, p);

    // 7) x1 = x + P@V   (K trimmed by causality)
    {
        dim3 grid(Dz/BN, Sz/BM, Bz);
        hgemm<0,false,false,true,false,true><<<grid, 256, SMEM_TOTAL>>>(
            p, vT, x1, nullptr, nullptr, x,
            Sz, Dz, Sz, 1.f, (long)Sz*Sz, (long)Dz*Sz, (long)Sz*Dz);
    }

    // 8) LN2 -> fp16
    ln_half_kernel<<<BSz, 256>>>(x1, gamma2, beta2, ln2);

    // 9) h = relu(ln2 @ w1 + b1) -> fp16
    {
        dim3 grid(Fz/BN, BSz/BM, 1);
        hgemm<1,true,true,false,false,false><<<grid, 256, SMEM_TOTAL>>>(
            ln2, w1T, nullptr, h, b1, nullptr, BSz, Fz, Dz, 1.f, 0, 0, 0);
    }

    // 10) out = x1 + h @ w2 + b2
    {
        dim3 grid(Dz/BN, BSz/BM, 1);
        hgemm<0,true,false,true,false,false><<<grid, 256, SMEM_TOTAL>>>(
            h, w2T, out, nullptr, b2, x1, BSz, Dz, Fz, 1.f, 0, 0, 0);
    }
}

// round 13
// speedup vs baseline: 2.7750x; 1.0616x over previous
#include <cuda_runtime.h>
#include <cuda_fp16.h>
#include <math.h>
#include <stdint.h>

// Problem constants
#define Bz 4
#define Sz 2048
#define Dz 1024
#define Fz 4096
#define BSz (Bz*Sz)   // 8192

// GEMM tiling (mma.sync fp16 path)
#define BM 128
#define BN 128
#define BK 64
#define ASTRIDE 72                    // K-major row stride elems (144B, conflict-free)
#define BSTRIDE_T 136                 // TRB row stride elems (272B, conflict-free)
#define TILE_A (128*ASTRIDE*2)        // 18432 B
#define TILE_B TILE_A                 // B tile slot (TRB uses 64*136*2=17408 <= this)
#define STAGE_BYTES (TILE_A + TILE_B) // 36864 B
#define SMEM_TOTAL (2*STAGE_BYTES)    // 73728 B (2 stages, 2 CTAs/SM)

// ---------------- scratch (static device globals; no allocation) ----------------
#define AL __align__(256)
__device__ AL __half s_ln1[(size_t)BSz*Dz];
__device__ AL __half s_qw [(size_t)Dz*Dz];
__device__ AL __half s_kw [(size_t)Dz*Dz];
__device__ AL __half s_vw [(size_t)Dz*Dz];
__device__ AL __half s_q  [(size_t)BSz*Dz];
__device__ AL __half s_k  [(size_t)BSz*Dz];
__device__ AL __half s_vh [(size_t)BSz*Dz];
__device__ AL float  s_sc [(size_t)Bz*Sz*Sz];
__device__ AL __half s_p  [(size_t)Bz*Sz*Sz];
__device__ AL float  s_x1 [(size_t)BSz*Dz];
__device__ AL __half s_ln2[(size_t)BSz*Dz];
__device__ AL __half s_w1 [(size_t)Dz*Fz];
__device__ AL __half s_w2 [(size_t)Fz*Dz];
__device__ AL __half s_h  [(size_t)BSz*Fz];

// ---------------- PTX helpers ----------------
__device__ __forceinline__ uint32_t smem_u32(const void* p) {
    uint32_t a;
    asm("{ .reg .u64 t; cvta.to.shared.u64 t, %1; cvt.u32.u64 %0, t; }" : "=r"(a) : "l"(p));
    return a;
}
__device__ __forceinline__ void cp16(uint32_t dst, const void* src) {
    asm volatile("cp.async.cg.shared.global [%0], [%1], 16;" :: "r"(dst), "l"(src));
}
__device__ __forceinline__ void cp_commit() { asm volatile("cp.async.commit_group;" ::: "memory"); }
__device__ __forceinline__ void cp_wait1()  { asm volatile("cp.async.wait_group 1;" ::: "memory"); }

__device__ __forceinline__ void ldm_x4(uint32_t* r, uint32_t addr) {
    asm volatile("ldmatrix.sync.aligned.m8n8.x4.shared.b16 {%0,%1,%2,%3}, [%4];"
                 : "=r"(r[0]), "=r"(r[1]), "=r"(r[2]), "=r"(r[3]) : "r"(addr));
}
__device__ __forceinline__ void ldm_x4_t(uint32_t* r, uint32_t addr) {
    asm volatile("ldmatrix.sync.aligned.m8n8.x4.trans.shared.b16 {%0,%1,%2,%3}, [%4];"
                 : "=r"(r[0]), "=r"(r[1]), "=r"(r[2]), "=r"(r[3]) : "r"(addr));
}
__device__ __forceinline__ void mma16816(float* c, const uint32_t* a, const uint32_t* b) {
    asm volatile(
        "mma.sync.aligned.m16n8k16.row.col.f32.f16.f16.f32 "
        "{%0,%1,%2,%3}, {%4,%5,%6,%7}, {%8,%9}, {%0,%1,%2,%3};"
        : "+f"(c[0]), "+f"(c[1]), "+f"(c[2]), "+f"(c[3])
        : "r"(a[0]), "r"(a[1]), "r"(a[2]), "r"(a[3]), "r"(b[0]), "r"(b[1]));
}
__device__ __forceinline__ uint32_t pack_half2(float a, float b) {
    __half2 h = __floats2half2_rn(a, b);
    return *(uint32_t*)&h;
}

// ---------------- reductions ----------------
__device__ __forceinline__ float warp_sum(float v) {
    #pragma unroll
    for (int o = 16; o > 0; o >>= 1) v += __shfl_xor_sync(0xffffffffu, v, o);
    return v;
}
__device__ __forceinline__ float warp_max(float v) {
    #pragma unroll
    for (int o = 16; o > 0; o >>= 1) v = fmaxf(v, __shfl_xor_sync(0xffffffffu, v, o));
    return v;
}
__device__ __forceinline__ float block_sum(float v, float* sm) {
    int wid = threadIdx.x >> 5, lid = threadIdx.x & 31;
    v = warp_sum(v);
    if (lid == 0) sm[wid] = v;
    __syncthreads();
    float r = (lid < 8) ? sm[lid] : 0.0f;
    r = warp_sum(r);
    r = __shfl_sync(0xffffffffu, r, 0);
    __syncthreads();
    return r;
}
__device__ __forceinline__ float block_max(float v, float* sm) {
    int wid = threadIdx.x >> 5, lid = threadIdx.x & 31;
    v = warp_max(v);
    if (lid == 0) sm[wid] = v;
    __syncthreads();
    float r = (lid < 8) ? sm[lid] : -INFINITY;
    r = warp_max(r);
    r = __shfl_sync(0xffffffffu, r, 0);
    __syncthreads();
    return r;
}

// ---------------- elementwise fp32 -> fp16 convert ----------------
__global__ void convert_half_kernel(const float* __restrict__ in,
                                    __half* __restrict__ out, int n) {
    int i = (blockIdx.x * 256 + threadIdx.x) * 4;
    if (i < n) {
        float4 v = *(const float4*)(in + i);
        uint2 o;
        o.x = pack_half2(v.x, v.y);
        o.y = pack_half2(v.z, v.w);
        *(uint2*)(out + i) = o;
    }
}

// ---------------- LN -> fp16 ----------------
__global__ void ln_half_kernel(const float* __restrict__ x,
                               const float* __restrict__ gamma,
                               const float* __restrict__ beta,
                               __half* __restrict__ out) {
    __shared__ float sm[8];
    size_t row = blockIdx.x;
    const float* xr = x + row * Dz;
    int t = threadIdx.x;
    float v[4];
    float s = 0.f, s2 = 0.f;
    #pragma unroll
    for (int i = 0; i < 4; i++) {
        float val = xr[t + i * 256];
        v[i] = val; s += val; s2 += val * val;
    }
    float tot  = block_sum(s,  sm);
    float tot2 = block_sum(s2, sm);
    float mean = tot * (1.0f / Dz);
    float var  = tot2 * (1.0f / Dz) - mean * mean;
    float inv  = rsqrtf(var + 1e-5f);
    #pragma unroll
    for (int i = 0; i < 4; i++) {
        int c = t + i * 256;
        float y = gamma[c] * ((v[i] - mean) * inv) + beta[c];
        out[row * Dz + c] = __float2half(y);
    }
}

// ---------------- causal softmax -> fp16 probs (masked-chunk load skip) ----------------
__global__ void softmax_half_kernel(const float* __restrict__ sc,
                                    __half* __restrict__ P) {
    __shared__ float sm[8];
    int row = blockIdx.x;
    int r = row & (Sz - 1);
    const float* src = sc + (size_t)row * Sz;
    int t = threadIdx.x;
    float v[8];
    float m = -INFINITY;
    #pragma unroll
    for (int i = 0; i < 8; i++) {
        int c = t + i * 256;
        float val = -INFINITY;
        if (i * 256 <= r) {
            val = src[c];
            val = (c <= r) ? val : -INFINITY;
        }
        v[i] = val;
        m = fmaxf(m, val);
    }
    m = block_max(m, sm);
    float s = 0.f;
    #pragma unroll
    for (int i = 0; i < 8; i++) {
        v[i] = expf(v[i] - m);
        s += v[i];
    }
    s = block_sum(s, sm);
    float inv = 1.0f / s;
    #pragma unroll
    for (int i = 0; i < 8; i++) {
        int c = t + i * 256;
        P[(size_t)row * Sz + c] = __float2half(v[i] * inv);
    }
}

// ---------------- fp16 GEMM via mma.sync (HMMA) ----------------
// TRB=0: C = alpha*A[M,K] @ B[N,K]^T  (B K-major, ldmatrix normal)
// TRB=1: C = alpha*A[M,K] @ B[K,N]    (B row-major, ldmatrix.trans; ldB = N)
// OUTM: 0 = fp32 C, 1 = fp16 C
template<int OUTM, bool BIAS_, bool RELU_, bool RES_, bool CAUSAL_, bool KTRIM_, bool TRB_>
__global__ void __launch_bounds__(256, 2)
hgemm(const __half* __restrict__ A, const __half* __restrict__ B,
      float* __restrict__ Cf, __half* __restrict__ Ch,
      const float* __restrict__ bias, const float* __restrict__ res,
      int M, int N, int K, float alpha, long sA, long sB, long sC)
{
    extern __shared__ char dynsmem[];
    const int bm = blockIdx.y * BM;
    const int bn = blockIdx.x * BN;
    if (CAUSAL_ && bn >= bm + BM) return;   // fully masked tile (softmax re-masks)

    const int tid  = threadIdx.x;
    const int wid  = tid >> 5;
    const int lane = tid & 31;
    const int warp_m = wid >> 1;     // 0..3  (rows, 32 each)
    const int warp_n = wid & 1;      // 0..1  (cols, 64 each)

    A += (size_t)blockIdx.z * sA;
    B += (size_t)blockIdx.z * sB;
    if (OUTM == 0) Cf += (size_t)blockIdx.z * sC;
    else           Ch += (size_t)blockIdx.z * sC;
    if (RES_) res += (size_t)blockIdx.z * sC;

    const uint32_t smem_base = smem_u32(dynsmem);

    const int kmax = KTRIM_ ? min(K, bm + BM) : K;
    const int nst  = kmax >> 6;      // BK=64

    auto issue_loads = [&](int s) {
        uint32_t sb = smem_base + (uint32_t)(s & 1) * STAGE_BYTES;
        int kt = s * BK;
        #pragma unroll
        for (int i = 0; i < 4; i++) {            // A: 1024 chunks (128 rows x 8)
            int id = i * 256 + tid;
            int r  = id >> 3;                    // 0..127
            int c8 = id & 7;
            cp16(sb + (uint32_t)(r * ASTRIDE + c8 * 8) * 2,
                 A + (size_t)(bm + r) * K + kt + c8 * 8);
        }
        if (!TRB_) {
            #pragma unroll
            for (int i = 0; i < 4; i++) {        // B: 1024 chunks (128 rows x 8)
                int id = i * 256 + tid;
                int r  = id >> 3;
                int c8 = id & 7;
                cp16(sb + TILE_A + (uint32_t)(r * ASTRIDE + c8 * 8) * 2,
                     B + (size_t)(bn + r) * K + kt + c8 * 8);
            }
        } else {
            #pragma unroll
            for (int i = 0; i < 4; i++) {        // B: 1024 chunks (64 rows x 16)
                int id  = i * 256 + tid;
                int r   = id >> 4;               // 0..63
                int c16 = id & 15;
                cp16(sb + TILE_A + (uint32_t)(r * BSTRIDE_T + c16 * 8) * 2,
                     B + (size_t)(kt + r) * N + bn + c16 * 8);
            }
        }
    };

    float acc[2][8][4];
    #pragma unroll
    for (int i = 0; i < 2; i++)
        #pragma unroll
        for (int j = 0; j < 8; j++)
            #pragma unroll
            for (int k = 0; k < 4; k++) acc[i][j][k] = 0.f;

    issue_loads(0); cp_commit();
    if (nst > 1) issue_loads(1);
    cp_commit();

    for (int s = 0; s < nst; s++) {
        cp_wait1();
        __syncthreads();

        uint32_t sb = smem_base + (uint32_t)(s & 1) * STAGE_BYTES;
        uint32_t aT = sb, bT = sb + TILE_A;

        #pragma unroll
        for (int k16 = 0; k16 < BK; k16 += 16) {
            uint32_t af[2][4];
            #pragma unroll
            for (int mi = 0; mi < 2; mi++) {
                uint32_t arow = (uint32_t)(warp_m * 32 + mi * 16 + (lane & 15));
                uint32_t aoff = (arow * ASTRIDE + (uint32_t)(k16 + (lane >> 4) * 8)) * 2;
                ldm_x4(af[mi], aT + aoff);
            }
            #pragma unroll
            for (int j = 0; j < 4; j++) {
                uint32_t bf[4];
                if (!TRB_) {
                    uint32_t brow = (uint32_t)(warp_n * 64 + j * 16 + ((lane >> 4) * 8) + (lane & 7));
                    uint32_t boff = (brow * ASTRIDE + (uint32_t)(k16 + ((lane >> 3) & 1) * 8)) * 2;
                    ldm_x4(bf, bT + boff);
                } else {
                    uint32_t krow = (uint32_t)(k16 + (lane & 15));
                    uint32_t ncol = (uint32_t)(warp_n * 64 + j * 16 + (lane >> 4) * 8);
                    ldm_x4_t(bf, bT + (krow * BSTRIDE_T + ncol) * 2);
                }
                #pragma unroll
                for (int mi = 0; mi < 2; mi++)
                    #pragma unroll
                    for (int sub = 0; sub < 2; sub++)
                        mma16816(acc[mi][j * 2 + sub], af[mi], bf + sub * 2);
            }
        }
        __syncthreads();
        if (s + 2 < nst) issue_loads(s + 2);
        cp_commit();
    }

    // ---------------- epilogue from register accumulators ----------------
    const int g = lane >> 2, t4 = lane & 3;
    #pragma unroll
    for (int mi = 0; mi < 2; mi++) {
        #pragma unroll
        for (int ni = 0; ni < 8; ni++) {
            int col = bn + warp_n * 64 + ni * 8 + t4 * 2;
            #pragma unroll
            for (int half = 0; half < 2; half++) {
                int row = bm + warp_m * 32 + mi * 16 + g + half * 8;
                float v0 = acc[mi][ni][half * 2 + 0] * alpha;
                float v1 = acc[mi][ni][half * 2 + 1] * alpha;
                if (BIAS_) { v0 += bias[col]; v1 += bias[col + 1]; }
                if (RELU_) { v0 = fmaxf(v0, 0.f); v1 = fmaxf(v1, 0.f); }
                if (RES_) {
                    float2 rv = *(const float2*)(res + (size_t)row * N + col);
                    v0 += rv.x; v1 += rv.y;
                }
                if (OUTM == 0) {
                    float2 o; o.x = v0; o.y = v1;
                    *(float2*)(Cf + (size_t)row * N + col) = o;
                } else {
                    *(uint32_t*)(Ch + (size_t)row * N + col) = pack_half2(v0, v1);
                }
            }
        }
    }
}

// ---------------- launcher ----------------
extern "C" void kernel_launch(void* const* d_in, const int* in_sizes, int n_in,
                              void* d_out, int out_size) {
    (void)in_sizes; (void)n_in; (void)out_size;
    const float* x      = (const float*)d_in[0];
    const float* Qw     = (const float*)d_in[1];
    const float* Kw     = (const float*)d_in[2];
    const float* Vw     = (const float*)d_in[3];
    const float* w1     = (const float*)d_in[4];
    const float* b1     = (const float*)d_in[5];
    const float* w2     = (const float*)d_in[6];
    const float* b2     = (const float*)d_in[7];
    const float* gamma1 = (const float*)d_in[8];
    const float* beta1  = (const float*)d_in[9];
    const float* gamma2 = (const float*)d_in[10];
    const float* beta2  = (const float*)d_in[11];
    float* out = (float*)d_out;

    __half *ln1,*qw,*kw,*vw,*q,*k,*vh,*p,*ln2,*w1h,*w2h,*h;
    float *sc,*x1;
    cudaGetSymbolAddress((void**)&ln1, s_ln1);
    cudaGetSymbolAddress((void**)&qw,  s_qw);
    cudaGetSymbolAddress((void**)&kw,  s_kw);
    cudaGetSymbolAddress((void**)&vw,  s_vw);
    cudaGetSymbolAddress((void**)&q,   s_q);
    cudaGetSymbolAddress((void**)&k,   s_k);
    cudaGetSymbolAddress((void**)&vh,  s_vh);
    cudaGetSymbolAddress((void**)&sc,  s_sc);
    cudaGetSymbolAddress((void**)&p,   s_p);
    cudaGetSymbolAddress((void**)&x1,  s_x1);
    cudaGetSymbolAddress((void**)&ln2, s_ln2);
    cudaGetSymbolAddress((void**)&w1h, s_w1);
    cudaGetSymbolAddress((void**)&w2h, s_w2);
    cudaGetSymbolAddress((void**)&h,   s_h);

    cudaFuncSetAttribute(hgemm<1,false,false,false,false,false,true >, cudaFuncAttributeMaxDynamicSharedMemorySize, SMEM_TOTAL);
    cudaFuncSetAttribute(hgemm<0,false,false,false,true ,false,false>, cudaFuncAttributeMaxDynamicSharedMemorySize, SMEM_TOTAL);
    cudaFuncSetAttribute(hgemm<0,false,false,true ,false,true ,true >, cudaFuncAttributeMaxDynamicSharedMemorySize, SMEM_TOTAL);
    cudaFuncSetAttribute(hgemm<1,true ,true ,false,false,false,true >, cudaFuncAttributeMaxDynamicSharedMemorySize, SMEM_TOTAL);
    cudaFuncSetAttribute(hgemm<0,true ,false,true ,false,false,true >, cudaFuncAttributeMaxDynamicSharedMemorySize, SMEM_TOTAL);

    const float scale = 1.0f / 32.0f;

    // 1) LN1 -> fp16
    ln_half_kernel<<<BSz, 256>>>(x, gamma1, beta1, ln1);

    // 2) weight converts fp32 -> fp16 (no transposes needed: TRB path)
    convert_half_kernel<<<(Dz*Dz)/1024, 256>>>(Qw, qw, Dz*Dz);
    convert_half_kernel<<<(Dz*Dz)/1024, 256>>>(Kw, kw, Dz*Dz);
    convert_half_kernel<<<(Dz*Dz)/1024, 256>>>(Vw, vw, Dz*Dz);
    convert_half_kernel<<<(Dz*Fz)/1024, 256>>>(w1, w1h, Dz*Fz);
    convert_half_kernel<<<(Fz*Dz)/1024, 256>>>(w2, w2h, Fz*Dz);

    // 3) Q, K, V projections -> fp16 (TRB: B = weight [K=D, N=D])
    {
        dim3 grid(Dz/BN, BSz/BM, 1);
        hgemm<1,false,false,false,false,false,true><<<grid, 256, SMEM_TOTAL>>>(
            ln1, qw, nullptr, q, nullptr, nullptr, BSz, Dz, Dz, 1.f, 0, 0, 0);
        hgemm<1,false,false,false,false,false,true><<<grid, 256, SMEM_TOTAL>>>(
            ln1, kw, nullptr, k, nullptr, nullptr, BSz, Dz, Dz, 1.f, 0, 0, 0);
        hgemm<1,false,false,false,false,false,true><<<grid, 256, SMEM_TOTAL>>>(
            ln1, vw, nullptr, vh, nullptr, nullptr, BSz, Dz, Dz, 1.f, 0, 0, 0);
    }

    // 4) scores = Q@K^T * scale (causal tile-skip), fp32 out; B=K fp16 [S,D] K-major
    {
        dim3 grid(Sz/BN, Sz/BM, Bz);
        hgemm<0,false,false,false,true,false,false><<<grid, 256, SMEM_TOTAL>>>(
            q, k, sc, nullptr, nullptr, nullptr,
            Sz, Sz, Dz, scale, (long)Sz*Dz, (long)Sz*Dz, (long)Sz*Sz);
    }

    // 5) causal softmax -> fp16 probs
    softmax_half_kernel<<<BSz, 256>>>(sc, p);

    // 6) x1 = x + P@V (TRB: B = V fp16 [K=S, N=D]; K trimmed by causality)
    {
        dim3 grid(Dz/BN, Sz/BM, Bz);
        hgemm<0,false,false,true,false,true,true><<<grid, 256, SMEM_TOTAL>>>(
            p, vh, x1, nullptr, nullptr, x,
            Sz, Dz, Sz, 1.f, (long)Sz*Sz, (long)Sz*Dz, (long)Sz*Dz);
    }

    // 7) LN2 -> fp16
    ln_half_kernel<<<BSz, 256>>>(x1, gamma2, beta2, ln2);

    // 8) h = relu(ln2 @ w1 + b1) -> fp16 (TRB: B = w1 [K=D, N=F])
    {
        dim3 grid(Fz/BN, BSz/BM, 1);
        hgemm<1,true,true,false,false,false,true><<<grid, 256, SMEM_TOTAL>>>(
            ln2, w1h, nullptr, h, b1, nullptr, BSz, Fz, Dz, 1.f, 0, 0, 0);
    }

    // 9) out = x1 + h @ w2 + b2 (TRB: B = w2 [K=F, N=D])
    {
        dim3 grid(Dz/BN, BSz/BM, 1);
        hgemm<0,true,false,true,false,false,true><<<grid, 256, SMEM_TOTAL>>>(
            h, w2h, out, nullptr, b2, x1, BSz, Dz, Fz, 1.f, 0, 0, 0);
    }
}

// round 15
// speedup vs baseline: 2.7976x; 1.0082x over previous
#include <cuda_runtime.h>
#include <cuda_fp16.h>
#include <math.h>
#include <stdint.h>

// Problem constants
#define Bz 4
#define Sz 2048
#define Dz 1024
#define Fz 4096
#define BSz (Bz*Sz)   // 8192

// GEMM tiling (mma.sync fp16 path)
#define BM 128
#define BN 128
#define BK 64
#define ASTRIDE 72                    // K-major row stride elems (144B, conflict-free)
#define BSTRIDE_T 136                 // TRB row stride elems (272B, conflict-free)
#define TILE_A (128*ASTRIDE*2)        // 18432 B
#define TILE_B TILE_A                 // B tile slot (TRB uses 64*136*2=17408 <= this)
#define STAGE_BYTES (TILE_A + TILE_B) // 36864 B
#define SMEM_TOTAL (2*STAGE_BYTES)    // 73728 B (2 stages, 2 CTAs/SM)

// ---------------- scratch (static device globals; no allocation) ----------------
#define AL __align__(256)
__device__ AL __half s_ln1[(size_t)BSz*Dz];
__device__ AL __half s_qw [(size_t)Dz*Dz];
__device__ AL __half s_kw [(size_t)Dz*Dz];
__device__ AL __half s_vw [(size_t)Dz*Dz];
__device__ AL __half s_q  [(size_t)BSz*Dz];
__device__ AL __half s_k  [(size_t)BSz*Dz];
__device__ AL __half s_vh [(size_t)BSz*Dz];
__device__ AL float  s_sc [(size_t)Bz*Sz*Sz];
__device__ AL __half s_p  [(size_t)Bz*Sz*Sz];
__device__ AL float  s_x1 [(size_t)BSz*Dz];
__device__ AL __half s_ln2[(size_t)BSz*Dz];
__device__ AL __half s_w1 [(size_t)Dz*Fz];
__device__ AL __half s_w2 [(size_t)Fz*Dz];
__device__ AL __half s_h  [(size_t)BSz*Fz];

// ---------------- PTX helpers ----------------
__device__ __forceinline__ uint32_t smem_u32(const void* p) {
    uint32_t a;
    asm("{ .reg .u64 t; cvta.to.shared.u64 t, %1; cvt.u32.u64 %0, t; }" : "=r"(a) : "l"(p));
    return a;
}
__device__ __forceinline__ void cp16(uint32_t dst, const void* src) {
    asm volatile("cp.async.cg.shared.global [%0], [%1], 16;" :: "r"(dst), "l"(src));
}
__device__ __forceinline__ void cp_commit() { asm volatile("cp.async.commit_group;" ::: "memory"); }
__device__ __forceinline__ void cp_wait1()  { asm volatile("cp.async.wait_group 1;" ::: "memory"); }

__device__ __forceinline__ void ldm_x4(uint32_t* r, uint32_t addr) {
    asm volatile("ldmatrix.sync.aligned.m8n8.x4.shared.b16 {%0,%1,%2,%3}, [%4];"
                 : "=r"(r[0]), "=r"(r[1]), "=r"(r[2]), "=r"(r[3]) : "r"(addr));
}
__device__ __forceinline__ void ldm_x4_t(uint32_t* r, uint32_t addr) {
    asm volatile("ldmatrix.sync.aligned.m8n8.x4.trans.shared.b16 {%0,%1,%2,%3}, [%4];"
                 : "=r"(r[0]), "=r"(r[1]), "=r"(r[2]), "=r"(r[3]) : "r"(addr));
}
__device__ __forceinline__ void mma16816(float* c, const uint32_t* a, const uint32_t* b) {
    asm volatile(
        "mma.sync.aligned.m16n8k16.row.col.f32.f16.f16.f32 "
        "{%0,%1,%2,%3}, {%4,%5,%6,%7}, {%8,%9}, {%0,%1,%2,%3};"
        : "+f"(c[0]), "+f"(c[1]), "+f"(c[2]), "+f"(c[3])
        : "r"(a[0]), "r"(a[1]), "r"(a[2]), "r"(a[3]), "r"(b[0]), "r"(b[1]));
}
__device__ __forceinline__ uint32_t pack_half2(float a, float b) {
    __half2 h = __floats2half2_rn(a, b);
    return *(uint32_t*)&h;
}

// ---------------- reductions ----------------
__device__ __forceinline__ float warp_sum(float v) {
    #pragma unroll
    for (int o = 16; o > 0; o >>= 1) v += __shfl_xor_sync(0xffffffffu, v, o);
    return v;
}
__device__ __forceinline__ float warp_max(float v) {
    #pragma unroll
    for (int o = 16; o > 0; o >>= 1) v = fmaxf(v, __shfl_xor_sync(0xffffffffu, v, o));
    return v;
}
__device__ __forceinline__ float block_sum(float v, float* sm) {
    int wid = threadIdx.x >> 5, lid = threadIdx.x & 31;
    v = warp_sum(v);
    if (lid == 0) sm[wid] = v;
    __syncthreads();
    float r = (lid < 8) ? sm[lid] : 0.0f;
    r = warp_sum(r);
    r = __shfl_sync(0xffffffffu, r, 0);
    __syncthreads();
    return r;
}
__device__ __forceinline__ float block_max(float v, float* sm) {
    int wid = threadIdx.x >> 5, lid = threadIdx.x & 31;
    v = warp_max(v);
    if (lid == 0) sm[wid] = v;
    __syncthreads();
    float r = (lid < 8) ? sm[lid] : -INFINITY;
    r = warp_max(r);
    r = __shfl_sync(0xffffffffu, r, 0);
    __syncthreads();
    return r;
}

// ---------------- merged fp32 -> fp16 convert of all 5 weights ----------------
__global__ void convert_all_kernel(const float* __restrict__ Qw, const float* __restrict__ Kw,
                                   const float* __restrict__ Vw, const float* __restrict__ w1,
                                   const float* __restrict__ w2,
                                   __half* __restrict__ qw, __half* __restrict__ kw,
                                   __half* __restrict__ vw, __half* __restrict__ w1h,
                                   __half* __restrict__ w2h) {
    long i = ((long)blockIdx.x * 256 + threadIdx.x) * 4;
    const long nD2 = (long)Dz * Dz, nDF = (long)Dz * Fz;
    const float* src; __half* dst; long off;
    if      (i < nD2)            { src = Qw; dst = qw;  off = i; }
    else if (i < 2*nD2)          { src = Kw; dst = kw;  off = i - nD2; }
    else if (i < 3*nD2)          { src = Vw; dst = vw;  off = i - 2*nD2; }
    else if (i < 3*nD2 + nDF)    { src = w1; dst = w1h; off = i - 3*nD2; }
    else                         { src = w2; dst = w2h; off = i - 3*nD2 - nDF; }
    float4 v = *(const float4*)(src + off);
    uint2 o;
    o.x = pack_half2(v.x, v.y);
    o.y = pack_half2(v.z, v.w);
    *(uint2*)(dst + off) = o;
}

// ---------------- LN -> fp16 ----------------
__global__ void ln_half_kernel(const float* __restrict__ x,
                               const float* __restrict__ gamma,
                               const float* __restrict__ beta,
                               __half* __restrict__ out) {
    __shared__ float sm[8];
    size_t row = blockIdx.x;
    const float* xr = x + row * Dz;
    int t = threadIdx.x;
    float v[4];
    float s = 0.f, s2 = 0.f;
    #pragma unroll
    for (int i = 0; i < 4; i++) {
        float val = xr[t + i * 256];
        v[i] = val; s += val; s2 += val * val;
    }
    float tot  = block_sum(s,  sm);
    float tot2 = block_sum(s2, sm);
    float mean = tot * (1.0f / Dz);
    float var  = tot2 * (1.0f / Dz) - mean * mean;
    float inv  = rsqrtf(var + 1e-5f);
    #pragma unroll
    for (int i = 0; i < 4; i++) {
        int c = t + i * 256;
        float y = gamma[c] * ((v[i] - mean) * inv) + beta[c];
        out[row * Dz + c] = __float2half(y);
    }
}

// ---------------- causal softmax -> fp16 probs ----------------
// load skip: chunks fully above diagonal; store skip: chunks beyond (r|127)
// (P@V K-trim never reads cols >= bm+128 = (r|127)+1)
__global__ void softmax_half_kernel(const float* __restrict__ sc,
                                    __half* __restrict__ P) {
    __shared__ float sm[8];
    int row = blockIdx.x;
    int r = row & (Sz - 1);
    const float* src = sc + (size_t)row * Sz;
    int t = threadIdx.x;
    float v[8];
    float m = -INFINITY;
    #pragma unroll
    for (int i = 0; i < 8; i++) {
        int c = t + i * 256;
        float val = -INFINITY;
        if (i * 256 <= r) {
            val = src[c];
            val = (c <= r) ? val : -INFINITY;
        }
        v[i] = val;
        m = fmaxf(m, val);
    }
    m = block_max(m, sm);
    float s = 0.f;
    #pragma unroll
    for (int i = 0; i < 8; i++) {
        v[i] = __expf(v[i] - m);
        s += v[i];
    }
    s = block_sum(s, sm);
    float inv = 1.0f / s;
    int wlim = r | 127;
    #pragma unroll
    for (int i = 0; i < 8; i++) {
        int c = t + i * 256;
        if (i * 256 <= wlim)
            P[(size_t)row * Sz + c] = __float2half(v[i] * inv);
    }
}

// ---------------- fp16 GEMM via mma.sync (HMMA) ----------------
// TRB=0: C = alpha*A[M,K] @ B[N,K]^T  (B K-major, ldmatrix normal)
// TRB=1: C = alpha*A[M,K] @ B[K,N]    (B row-major, ldmatrix.trans; ldB = N)
// OUTM: 0 = fp32 C, 1 = fp16 C
template<int OUTM, bool BIAS_, bool RELU_, bool RES_, bool CAUSAL_, bool KTRIM_, bool TRB_>
__global__ void __launch_bounds__(256, 2)
hgemm(const __half* __restrict__ A, const __half* __restrict__ B,
      float* __restrict__ Cf, __half* __restrict__ Ch,
      const float* __restrict__ bias, const float* __restrict__ res,
      int M, int N, int K, float alpha, long sA, long sB, long sC)
{
    extern __shared__ char dynsmem[];
    const int bm = blockIdx.y * BM;
    const int bn = blockIdx.x * BN;
    if (CAUSAL_ && bn >= bm + BM) return;   // fully masked tile (softmax re-masks)

    const int tid  = threadIdx.x;
    const int wid  = tid >> 5;
    const int lane = tid & 31;
    const int warp_m = wid >> 1;     // 0..3  (rows, 32 each)
    const int warp_n = wid & 1;      // 0..1  (cols, 64 each)

    A += (size_t)blockIdx.z * sA;
    B += (size_t)blockIdx.z * sB;
    if (OUTM == 0) Cf += (size_t)blockIdx.z * sC;
    else           Ch += (size_t)blockIdx.z * sC;
    if (RES_) res += (size_t)blockIdx.z * sC;

    const uint32_t smem_base = smem_u32(dynsmem);

    const int kmax = KTRIM_ ? min(K, bm + BM) : K;
    const int nst  = kmax >> 6;      // BK=64

    auto issue_loads = [&](int s) {
        uint32_t sb = smem_base + (uint32_t)(s & 1) * STAGE_BYTES;
        int kt = s * BK;
        #pragma unroll
        for (int i = 0; i < 4; i++) {            // A: 1024 chunks (128 rows x 8)
            int id = i * 256 + tid;
            int r  = id >> 3;                    // 0..127
            int c8 = id & 7;
            cp16(sb + (uint32_t)(r * ASTRIDE + c8 * 8) * 2,
                 A + (size_t)(bm + r) * K + kt + c8 * 8);
        }
        if (!TRB_) {
            #pragma unroll
            for (int i = 0; i < 4; i++) {        // B: 1024 chunks (128 rows x 8)
                int id = i * 256 + tid;
                int r  = id >> 3;
                int c8 = id & 7;
                cp16(sb + TILE_A + (uint32_t)(r * ASTRIDE + c8 * 8) * 2,
                     B + (size_t)(bn + r) * K + kt + c8 * 8);
            }
        } else {
            #pragma unroll
            for (int i = 0; i < 4; i++) {        // B: 1024 chunks (64 rows x 16)
                int id  = i * 256 + tid;
                int r   = id >> 4;               // 0..63
                int c16 = id & 15;
                cp16(sb + TILE_A + (uint32_t)(r * BSTRIDE_T + c16 * 8) * 2,
                     B + (size_t)(kt + r) * N + bn + c16 * 8);
            }
        }
    };

    float acc[2][8][4];
    #pragma unroll
    for (int i = 0; i < 2; i++)
        #pragma unroll
        for (int j = 0; j < 8; j++)
            #pragma unroll
            for (int k = 0; k < 4; k++) acc[i][j][k] = 0.f;

    issue_loads(0); cp_commit();
    if (nst > 1) issue_loads(1);
    cp_commit();

    for (int s = 0; s < nst; s++) {
        cp_wait1();
        __syncthreads();

        uint32_t sb = smem_base + (uint32_t)(s & 1) * STAGE_BYTES;
        uint32_t aT = sb, bT = sb + TILE_A;

        #pragma unroll
        for (int k16 = 0; k16 < BK; k16 += 16) {
            uint32_t af[2][4];
            #pragma unroll
            for (int mi = 0; mi < 2; mi++) {
                uint32_t arow = (uint32_t)(warp_m * 32 + mi * 16 + (lane & 15));
                uint32_t aoff = (arow * ASTRIDE + (uint32_t)(k16 + (lane >> 4) * 8)) * 2;
                ldm_x4(af[mi], aT + aoff);
            }
            #pragma unroll
            for (int j = 0; j < 4; j++) {
                uint32_t bf[4];
                if (!TRB_) {
                    uint32_t brow = (uint32_t)(warp_n * 64 + j * 16 + ((lane >> 4) * 8) + (lane & 7));
                    uint32_t boff = (brow * ASTRIDE + (uint32_t)(k16 + ((lane >> 3) & 1) * 8)) * 2;
                    ldm_x4(bf, bT + boff);
                } else {
                    uint32_t krow = (uint32_t)(k16 + (lane & 15));
                    uint32_t ncol = (uint32_t)(warp_n * 64 + j * 16 + (lane >> 4) * 8);
                    ldm_x4_t(bf, bT + (krow * BSTRIDE_T + ncol) * 2);
                }
                #pragma unroll
                for (int mi = 0; mi < 2; mi++)
                    #pragma unroll
                    for (int sub = 0; sub < 2; sub++)
                        mma16816(acc[mi][j * 2 + sub], af[mi], bf + sub * 2);
            }
        }
        __syncthreads();
        if (s + 2 < nst) issue_loads(s + 2);
        cp_commit();
    }

    // ---------------- epilogue from register accumulators ----------------
    const int g = lane >> 2, t4 = lane & 3;
    #pragma unroll
    for (int mi = 0; mi < 2; mi++) {
        #pragma unroll
        for (int ni = 0; ni < 8; ni++) {
            int col = bn + warp_n * 64 + ni * 8 + t4 * 2;
            #pragma unroll
            for (int half = 0; half < 2; half++) {
                int row = bm + warp_m * 32 + mi * 16 + g + half * 8;
                float v0 = acc[mi][ni][half * 2 + 0] * alpha;
                float v1 = acc[mi][ni][half * 2 + 1] * alpha;
                if (BIAS_) { v0 += bias[col]; v1 += bias[col + 1]; }
                if (RELU_) { v0 = fmaxf(v0, 0.f); v1 = fmaxf(v1, 0.f); }
                if (RES_) {
                    float2 rv = *(const float2*)(res + (size_t)row * N + col);
                    v0 += rv.x; v1 += rv.y;
                }
                if (OUTM == 0) {
                    float2 o; o.x = v0; o.y = v1;
                    *(float2*)(Cf + (size_t)row * N + col) = o;
                } else {
                    *(uint32_t*)(Ch + (size_t)row * N + col) = pack_half2(v0, v1);
                }
            }
        }
    }
}

// ---------------- launcher ----------------
extern "C" void kernel_launch(void* const* d_in, const int* in_sizes, int n_in,
                              void* d_out, int out_size) {
    (void)in_sizes; (void)n_in; (void)out_size;
    const float* x      = (const float*)d_in[0];
    const float* Qw     = (const float*)d_in[1];
    const float* Kw     = (const float*)d_in[2];
    const float* Vw     = (const float*)d_in[3];
    const float* w1     = (const float*)d_in[4];
    const float* b1     = (const float*)d_in[5];
    const float* w2     = (const float*)d_in[6];
    const float* b2     = (const float*)d_in[7];
    const float* gamma1 = (const float*)d_in[8];
    const float* beta1  = (const float*)d_in[9];
    const float* gamma2 = (const float*)d_in[10];
    const float* beta2  = (const float*)d_in[11];
    float* out = (float*)d_out;

    __half *ln1,*qw,*kw,*vw,*q,*k,*vh,*p,*ln2,*w1h,*w2h,*h;
    float *sc,*x1;
    cudaGetSymbolAddress((void**)&ln1, s_ln1);
    cudaGetSymbolAddress((void**)&qw,  s_qw);
    cudaGetSymbolAddress((void**)&kw,  s_kw);
    cudaGetSymbolAddress((void**)&vw,  s_vw);
    cudaGetSymbolAddress((void**)&q,   s_q);
    cudaGetSymbolAddress((void**)&k,   s_k);
    cudaGetSymbolAddress((void**)&vh,  s_vh);
    cudaGetSymbolAddress((void**)&sc,  s_sc);
    cudaGetSymbolAddress((void**)&p,   s_p);
    cudaGetSymbolAddress((void**)&x1,  s_x1);
    cudaGetSymbolAddress((void**)&ln2, s_ln2);
    cudaGetSymbolAddress((void**)&w1h, s_w1);
    cudaGetSymbolAddress((void**)&w2h, s_w2);
    cudaGetSymbolAddress((void**)&h,   s_h);

    cudaFuncSetAttribute(hgemm<1,false,false,false,false,false,true >, cudaFuncAttributeMaxDynamicSharedMemorySize, SMEM_TOTAL);
    cudaFuncSetAttribute(hgemm<0,false,false,false,true ,false,false>, cudaFuncAttributeMaxDynamicSharedMemorySize, SMEM_TOTAL);
    cudaFuncSetAttribute(hgemm<0,false,false,true ,false,true ,true >, cudaFuncAttributeMaxDynamicSharedMemorySize, SMEM_TOTAL);
    cudaFuncSetAttribute(hgemm<1,true ,true ,false,false,false,true >, cudaFuncAttributeMaxDynamicSharedMemorySize, SMEM_TOTAL);
    cudaFuncSetAttribute(hgemm<0,true ,false,true ,false,false,true >, cudaFuncAttributeMaxDynamicSharedMemorySize, SMEM_TOTAL);

    const float scale = 1.0f / 32.0f;

    // 1) LN1 -> fp16 (critical path for QKV; launch first)
    ln_half_kernel<<<BSz, 256>>>(x, gamma1, beta1, ln1);

    // 2) merged weight converts fp32 -> fp16 (single launch)
    {
        long total = 3L*Dz*Dz + 2L*(long)Dz*Fz;   // 11534336 elems
        convert_all_kernel<<<(unsigned)(total/1024), 256>>>(
            Qw, Kw, Vw, w1, w2, qw, kw, vw, w1h, w2h);
    }

    // 3) Q, K, V projections -> fp16 (TRB: B = weight [K=D, N=D])
    {
        dim3 grid(Dz/BN, BSz/BM, 1);
        hgemm<1,false,false,false,false,false,true><<<grid, 256, SMEM_TOTAL>>>(
            ln1, qw, nullptr, q, nullptr, nullptr, BSz, Dz, Dz, 1.f, 0, 0, 0);
        hgemm<1,false,false,false,false,false,true><<<grid, 256, SMEM_TOTAL>>>(
            ln1, kw, nullptr, k, nullptr, nullptr, BSz, Dz, Dz, 1.f, 0, 0, 0);
        hgemm<1,false,false,false,false,false,true><<<grid, 256, SMEM_TOTAL>>>(
            ln1, vw, nullptr, vh, nullptr, nullptr, BSz, Dz, Dz, 1.f, 0, 0, 0);
    }

    // 4) scores = Q@K^T * scale (causal tile-skip), fp32 out; B=K fp16 [S,D] K-major
    {
        dim3 grid(Sz/BN, Sz/BM, Bz);
        hgemm<0,false,false,false,true,false,false><<<grid, 256, SMEM_TOTAL>>>(
            q, k, sc, nullptr, nullptr, nullptr,
            Sz, Sz, Dz, scale, (long)Sz*Dz, (long)Sz*Dz, (long)Sz*Sz);
    }

    // 5) causal softmax -> fp16 probs
    softmax_half_kernel<<<BSz, 256>>>(sc, p);

    // 6) x1 = x + P@V (TRB: B = V fp16 [K=S, N=D]; K trimmed by causality)
    {
        dim3 grid(Dz/BN, Sz/BM, Bz);
        hgemm<0,false,false,true,false,true,true><<<grid, 256, SMEM_TOTAL>>>(
            p, vh, x1, nullptr, nullptr, x,
            Sz, Dz, Sz, 1.f, (long)Sz*Sz, (long)Sz*Dz, (long)Sz*Dz);
    }

    // 7) LN2 -> fp16
    ln_half_kernel<<<BSz, 256>>>(x1, gamma2, beta2, ln2);

    // 8) h = relu(ln2 @ w1 + b1) -> fp16 (TRB: B = w1 [K=D, N=F])
    {
        dim3 grid(Fz/BN, BSz/BM, 1);
        hgemm<1,true,true,false,false,false,true><<<grid, 256, SMEM_TOTAL>>>(
            ln2, w1h, nullptr, h, b1, nullptr, BSz, Fz, Dz, 1.f, 0, 0, 0);
    }

    // 9) out = x1 + h @ w2 + b2 (TRB: B = w2 [K=F, N=D])
    {
        dim3 grid(Dz/BN, BSz/BM, 1);
        hgemm<0,true,false,true,false,false,true><<<grid, 256, SMEM_TOTAL>>>(
            h, w2h, out, nullptr, b2, x1, BSz, Dz, Fz, 1.f, 0, 0, 0);
    }
}

// round 16
// speedup vs baseline: 2.8018x; 1.0015x over previous
#include <cuda_runtime.h>
#include <cuda_fp16.h>
#include <math.h>
#include <stdint.h>

// Problem constants
#define Bz 4
#define Sz 2048
#define Dz 1024
#define Fz 4096
#define BSz (Bz*Sz)   // 8192

// GEMM tiling (mma.sync fp16 path)
#define BM 128
#define BN 128
#define BK 64
#define ASTRIDE 72                    // K-major row stride elems (144B, conflict-free)
#define BSTRIDE_T 136                 // TRB row stride elems (272B, conflict-free)
#define TILE_A (128*ASTRIDE*2)        // 18432 B
#define TILE_B TILE_A                 // B tile slot (TRB uses 64*136*2=17408 <= this)
#define STAGE_BYTES (TILE_A + TILE_B) // 36864 B
#define NSTAGE 3
#define SMEM_TOTAL (NSTAGE*STAGE_BYTES)  // 110592 B/CTA; 2 CTAs = 221184 <= 228KB/SM

// ---------------- scratch (static device globals; no allocation) ----------------
#define AL __align__(256)
__device__ AL __half s_ln1[(size_t)BSz*Dz];
__device__ AL __half s_qw [(size_t)Dz*Dz];
__device__ AL __half s_kw [(size_t)Dz*Dz];
__device__ AL __half s_vw [(size_t)Dz*Dz];
__device__ AL __half s_q  [(size_t)BSz*Dz];
__device__ AL __half s_k  [(size_t)BSz*Dz];
__device__ AL __half s_vh [(size_t)BSz*Dz];
__device__ AL float  s_sc [(size_t)Bz*Sz*Sz];
__device__ AL __half s_p  [(size_t)Bz*Sz*Sz];
__device__ AL float  s_x1 [(size_t)BSz*Dz];
__device__ AL __half s_ln2[(size_t)BSz*Dz];
__device__ AL __half s_w1 [(size_t)Dz*Fz];
__device__ AL __half s_w2 [(size_t)Fz*Dz];
__device__ AL __half s_h  [(size_t)BSz*Fz];

// ---------------- PTX helpers ----------------
__device__ __forceinline__ uint32_t smem_u32(const void* p) {
    uint32_t a;
    asm("{ .reg .u64 t; cvta.to.shared.u64 t, %1; cvt.u32.u64 %0, t; }" : "=r"(a) : "l"(p));
    return a;
}
__device__ __forceinline__ void cp16(uint32_t dst, const void* src) {
    asm volatile("cp.async.cg.shared.global [%0], [%1], 16;" :: "r"(dst), "l"(src));
}
__device__ __forceinline__ void cp_commit() { asm volatile("cp.async.commit_group;" ::: "memory"); }
__device__ __forceinline__ void cp_wait1()  { asm volatile("cp.async.wait_group 1;" ::: "memory"); }

__device__ __forceinline__ void ldm_x4(uint32_t* r, uint32_t addr) {
    asm volatile("ldmatrix.sync.aligned.m8n8.x4.shared.b16 {%0,%1,%2,%3}, [%4];"
                 : "=r"(r[0]), "=r"(r[1]), "=r"(r[2]), "=r"(r[3]) : "r"(addr));
}
__device__ __forceinline__ void ldm_x4_t(uint32_t* r, uint32_t addr) {
    asm volatile("ldmatrix.sync.aligned.m8n8.x4.trans.shared.b16 {%0,%1,%2,%3}, [%4];"
                 : "=r"(r[0]), "=r"(r[1]), "=r"(r[2]), "=r"(r[3]) : "r"(addr));
}
__device__ __forceinline__ void mma16816(float* c, const uint32_t* a, const uint32_t* b) {
    asm volatile(
        "mma.sync.aligned.m16n8k16.row.col.f32.f16.f16.f32 "
        "{%0,%1,%2,%3}, {%4,%5,%6,%7}, {%8,%9}, {%0,%1,%2,%3};"
        : "+f"(c[0]), "+f"(c[1]), "+f"(c[2]), "+f"(c[3])
        : "r"(a[0]), "r"(a[1]), "r"(a[2]), "r"(a[3]), "r"(b[0]), "r"(b[1]));
}
__device__ __forceinline__ uint32_t pack_half2(float a, float b) {
    __half2 h = __floats2half2_rn(a, b);
    return *(uint32_t*)&h;
}

// ---------------- reductions ----------------
__device__ __forceinline__ float warp_sum(float v) {
    #pragma unroll
    for (int o = 16; o > 0; o >>= 1) v += __shfl_xor_sync(0xffffffffu, v, o);
    return v;
}
__device__ __forceinline__ float warp_max(float v) {
    #pragma unroll
    for (int o = 16; o > 0; o >>= 1) v = fmaxf(v, __shfl_xor_sync(0xffffffffu, v, o));
    return v;
}
__device__ __forceinline__ float block_sum(float v, float* sm) {
    int wid = threadIdx.x >> 5, lid = threadIdx.x & 31;
    v = warp_sum(v);
    if (lid == 0) sm[wid] = v;
    __syncthreads();
    float r = (lid < 8) ? sm[lid] : 0.0f;
    r = warp_sum(r);
    r = __shfl_sync(0xffffffffu, r, 0);
    __syncthreads();
    return r;
}
__device__ __forceinline__ float block_max(float v, float* sm) {
    int wid = threadIdx.x >> 5, lid = threadIdx.x & 31;
    v = warp_max(v);
    if (lid == 0) sm[wid] = v;
    __syncthreads();
    float r = (lid < 8) ? sm[lid] : -INFINITY;
    r = warp_max(r);
    r = __shfl_sync(0xffffffffu, r, 0);
    __syncthreads();
    return r;
}

// ---------------- merged fp32 -> fp16 convert of all 5 weights ----------------
__global__ void convert_all_kernel(const float* __restrict__ Qw, const float* __restrict__ Kw,
                                   const float* __restrict__ Vw, const float* __restrict__ w1,
                                   const float* __restrict__ w2,
                                   __half* __restrict__ qw, __half* __restrict__ kw,
                                   __half* __restrict__ vw, __half* __restrict__ w1h,
                                   __half* __restrict__ w2h) {
    long i = ((long)blockIdx.x * 256 + threadIdx.x) * 4;
    const long nD2 = (long)Dz * Dz, nDF = (long)Dz * Fz;
    const float* src; __half* dst; long off;
    if      (i < nD2)            { src = Qw; dst = qw;  off = i; }
    else if (i < 2*nD2)          { src = Kw; dst = kw;  off = i - nD2; }
    else if (i < 3*nD2)          { src = Vw; dst = vw;  off = i - 2*nD2; }
    else if (i < 3*nD2 + nDF)    { src = w1; dst = w1h; off = i - 3*nD2; }
    else                         { src = w2; dst = w2h; off = i - 3*nD2 - nDF; }
    float4 v = *(const float4*)(src + off);
    uint2 o;
    o.x = pack_half2(v.x, v.y);
    o.y = pack_half2(v.z, v.w);
    *(uint2*)(dst + off) = o;
}

// ---------------- LN -> fp16 ----------------
__global__ void ln_half_kernel(const float* __restrict__ x,
                               const float* __restrict__ gamma,
                               const float* __restrict__ beta,
                               __half* __restrict__ out) {
    __shared__ float sm[8];
    size_t row = blockIdx.x;
    const float* xr = x + row * Dz;
    int t = threadIdx.x;
    float v[4];
    float s = 0.f, s2 = 0.f;
    #pragma unroll
    for (int i = 0; i < 4; i++) {
        float val = xr[t + i * 256];
        v[i] = val; s += val; s2 += val * val;
    }
    float tot  = block_sum(s,  sm);
    float tot2 = block_sum(s2, sm);
    float mean = tot * (1.0f / Dz);
    float var  = tot2 * (1.0f / Dz) - mean * mean;
    float inv  = rsqrtf(var + 1e-5f);
    #pragma unroll
    for (int i = 0; i < 4; i++) {
        int c = t + i * 256;
        float y = gamma[c] * ((v[i] - mean) * inv) + beta[c];
        out[row * Dz + c] = __float2half(y);
    }
}

// ---------------- causal softmax -> fp16 probs ----------------
// load skip: chunks fully above diagonal; store skip: chunks beyond (r|127)
// (P@V K-trim never reads cols >= bm+128 = (r|127)+1)
__global__ void softmax_half_kernel(const float* __restrict__ sc,
                                    __half* __restrict__ P) {
    __shared__ float sm[8];
    int row = blockIdx.x;
    int r = row & (Sz - 1);
    const float* src = sc + (size_t)row * Sz;
    int t = threadIdx.x;
    float v[8];
    float m = -INFINITY;
    #pragma unroll
    for (int i = 0; i < 8; i++) {
        int c = t + i * 256;
        float val = -INFINITY;
        if (i * 256 <= r) {
            val = src[c];
            val = (c <= r) ? val : -INFINITY;
        }
        v[i] = val;
        m = fmaxf(m, val);
    }
    m = block_max(m, sm);
    float s = 0.f;
    #pragma unroll
    for (int i = 0; i < 8; i++) {
        v[i] = __expf(v[i] - m);
        s += v[i];
    }
    s = block_sum(s, sm);
    float inv = 1.0f / s;
    int wlim = r | 127;
    #pragma unroll
    for (int i = 0; i < 8; i++) {
        int c = t + i * 256;
        if (i * 256 <= wlim)
            P[(size_t)row * Sz + c] = __float2half(v[i] * inv);
    }
}

// ---------------- fp16 GEMM via mma.sync (HMMA) ----------------
// TRB=0: C = alpha*A[M,K] @ B[N,K]^T  (B K-major, ldmatrix normal)
// TRB=1: C = alpha*A[M,K] @ B[K,N]    (B row-major, ldmatrix.trans; ldB = N)
// OUTM: 0 = fp32 C, 1 = fp16 C
// 3-stage cp.async pipeline, ONE barrier per stage, prefetch distance 2 stages.
template<int OUTM, bool BIAS_, bool RELU_, bool RES_, bool CAUSAL_, bool KTRIM_, bool TRB_>
__global__ void __launch_bounds__(256, 2)
hgemm(const __half* __restrict__ A, const __half* __restrict__ B,
      float* __restrict__ Cf, __half* __restrict__ Ch,
      const float* __restrict__ bias, const float* __restrict__ res,
      int M, int N, int K, float alpha, long sA, long sB, long sC)
{
    extern __shared__ char dynsmem[];
    const int bm = blockIdx.y * BM;
    const int bn = blockIdx.x * BN;
    if (CAUSAL_ && bn >= bm + BM) return;   // fully masked tile (softmax re-masks)

    const int tid  = threadIdx.x;
    const int wid  = tid >> 5;
    const int lane = tid & 31;
    const int warp_m = wid >> 1;     // 0..3  (rows, 32 each)
    const int warp_n = wid & 1;      // 0..1  (cols, 64 each)

    A += (size_t)blockIdx.z * sA;
    B += (size_t)blockIdx.z * sB;
    if (OUTM == 0) Cf += (size_t)blockIdx.z * sC;
    else           Ch += (size_t)blockIdx.z * sC;
    if (RES_) res += (size_t)blockIdx.z * sC;

    const uint32_t smem_base = smem_u32(dynsmem);

    const int kmax = KTRIM_ ? min(K, bm + BM) : K;
    const int nst  = kmax >> 6;      // BK=64

    auto issue_loads = [&](int s) {
        uint32_t sb = smem_base + (uint32_t)(s % NSTAGE) * STAGE_BYTES;
        int kt = s * BK;
        #pragma unroll
        for (int i = 0; i < 4; i++) {            // A: 1024 chunks (128 rows x 8)
            int id = i * 256 + tid;
            int r  = id >> 3;                    // 0..127
            int c8 = id & 7;
            cp16(sb + (uint32_t)(r * ASTRIDE + c8 * 8) * 2,
                 A + (size_t)(bm + r) * K + kt + c8 * 8);
        }
        if (!TRB_) {
            #pragma unroll
            for (int i = 0; i < 4; i++) {        // B: 1024 chunks (128 rows x 8)
                int id = i * 256 + tid;
                int r  = id >> 3;
                int c8 = id & 7;
                cp16(sb + TILE_A + (uint32_t)(r * ASTRIDE + c8 * 8) * 2,
                     B + (size_t)(bn + r) * K + kt + c8 * 8);
            }
        } else {
            #pragma unroll
            for (int i = 0; i < 4; i++) {        // B: 1024 chunks (64 rows x 16)
                int id  = i * 256 + tid;
                int r   = id >> 4;               // 0..63
                int c16 = id & 15;
                cp16(sb + TILE_A + (uint32_t)(r * BSTRIDE_T + c16 * 8) * 2,
                     B + (size_t)(kt + r) * N + bn + c16 * 8);
            }
        }
    };

    float acc[2][8][4];
    #pragma unroll
    for (int i = 0; i < 2; i++)
        #pragma unroll
        for (int j = 0; j < 8; j++)
            #pragma unroll
            for (int k = 0; k < 4; k++) acc[i][j][k] = 0.f;

    issue_loads(0); cp_commit();
    if (nst > 1) issue_loads(1);
    cp_commit();

    for (int s = 0; s < nst; s++) {
        cp_wait1();                  // stage s complete (s+1 may still be in flight)
        __syncthreads();             // all warps done computing stage s-1 -> buffer (s+2)%3 free

        if (s + 2 < nst) issue_loads(s + 2);
        cp_commit();                 // commit every iteration (keeps group accounting uniform)

        uint32_t sb = smem_base + (uint32_t)(s % NSTAGE) * STAGE_BYTES;
        uint32_t aT = sb, bT = sb + TILE_A;

        #pragma unroll
        for (int k16 = 0; k16 < BK; k16 += 16) {
            uint32_t af[2][4];
            #pragma unroll
            for (int mi = 0; mi < 2; mi++) {
                uint32_t arow = (uint32_t)(warp_m * 32 + mi * 16 + (lane & 15));
                uint32_t aoff = (arow * ASTRIDE + (uint32_t)(k16 + (lane >> 4) * 8)) * 2;
                ldm_x4(af[mi], aT + aoff);
            }
            #pragma unroll
            for (int j = 0; j < 4; j++) {
                uint32_t bf[4];
                if (!TRB_) {
                    uint32_t brow = (uint32_t)(warp_n * 64 + j * 16 + ((lane >> 4) * 8) + (lane & 7));
                    uint32_t boff = (brow * ASTRIDE + (uint32_t)(k16 + ((lane >> 3) & 1) * 8)) * 2;
                    ldm_x4(bf, bT + boff);
                } else {
                    uint32_t krow = (uint32_t)(k16 + (lane & 15));
                    uint32_t ncol = (uint32_t)(warp_n * 64 + j * 16 + (lane >> 4) * 8);
                    ldm_x4_t(bf, bT + (krow * BSTRIDE_T + ncol) * 2);
                }
                #pragma unroll
                for (int mi = 0; mi < 2; mi++)
                    #pragma unroll
                    for (int sub = 0; sub < 2; sub++)
                        mma16816(acc[mi][j * 2 + sub], af[mi], bf + sub * 2);
            }
        }
    }

    // ---------------- epilogue from register accumulators ----------------
    const int g = lane >> 2, t4 = lane & 3;
    #pragma unroll
    for (int mi = 0; mi < 2; mi++) {
        #pragma unroll
        for (int ni = 0; ni < 8; ni++) {
            int col = bn + warp_n * 64 + ni * 8 + t4 * 2;
            #pragma unroll
            for (int half = 0; half < 2; half++) {
                int row = bm + warp_m * 32 + mi * 16 + g + half * 8;
                float v0 = acc[mi][ni][half * 2 + 0] * alpha;
                float v1 = acc[mi][ni][half * 2 + 1] * alpha;
                if (BIAS_) { v0 += bias[col]; v1 += bias[col + 1]; }
                if (RELU_) { v0 = fmaxf(v0, 0.f); v1 = fmaxf(v1, 0.f); }
                if (RES_) {
                    float2 rv = *(const float2*)(res + (size_t)row * N + col);
                    v0 += rv.x; v1 += rv.y;
                }
                if (OUTM == 0) {
                    float2 o; o.x = v0; o.y = v1;
                    *(float2*)(Cf + (size_t)row * N + col) = o;
                } else {
                    *(uint32_t*)(Ch + (size_t)row * N + col) = pack_half2(v0, v1);
                }
            }
        }
    }
}

// ---------------- launcher ----------------
extern "C" void kernel_launch(void* const* d_in, const int* in_sizes, int n_in,
                              void* d_out, int out_size) {
    (void)in_sizes; (void)n_in; (void)out_size;
    const float* x      = (const float*)d_in[0];
    const float* Qw     = (const float*)d_in[1];
    const float* Kw     = (const float*)d_in[2];
    const float* Vw     = (const float*)d_in[3];
    const float* w1     = (const float*)d_in[4];
    const float* b1     = (const float*)d_in[5];
    const float* w2     = (const float*)d_in[6];
    const float* b2     = (const float*)d_in[7];
    const float* gamma1 = (const float*)d_in[8];
    const float* beta1  = (const float*)d_in[9];
    const float* gamma2 = (const float*)d_in[10];
    const float* beta2  = (const float*)d_in[11];
    float* out = (float*)d_out;

    __half *ln1,*qw,*kw,*vw,*q,*k,*vh,*p,*ln2,*w1h,*w2h,*h;
    float *sc,*x1;
    cudaGetSymbolAddress((void**)&ln1, s_ln1);
    cudaGetSymbolAddress((void**)&qw,  s_qw);
    cudaGetSymbolAddress((void**)&kw,  s_kw);
    cudaGetSymbolAddress((void**)&vw,  s_vw);
    cudaGetSymbolAddress((void**)&q,   s_q);
    cudaGetSymbolAddress((void**)&k,   s_k);
    cudaGetSymbolAddress((void**)&vh,  s_vh);
    cudaGetSymbolAddress((void**)&sc,  s_sc);
    cudaGetSymbolAddress((void**)&p,   s_p);
    cudaGetSymbolAddress((void**)&x1,  s_x1);
    cudaGetSymbolAddress((void**)&ln2, s_ln2);
    cudaGetSymbolAddress((void**)&w1h, s_w1);
    cudaGetSymbolAddress((void**)&w2h, s_w2);
    cudaGetSymbolAddress((void**)&h,   s_h);

    cudaFuncSetAttribute(hgemm<1,false,false,false,false,false,true >, cudaFuncAttributeMaxDynamicSharedMemorySize, SMEM_TOTAL);
    cudaFuncSetAttribute(hgemm<0,false,false,false,true ,false,false>, cudaFuncAttributeMaxDynamicSharedMemorySize, SMEM_TOTAL);
    cudaFuncSetAttribute(hgemm<0,false,false,true ,false,true ,true >, cudaFuncAttributeMaxDynamicSharedMemorySize, SMEM_TOTAL);
    cudaFuncSetAttribute(hgemm<1,true ,true ,false,false,false,true >, cudaFuncAttributeMaxDynamicSharedMemorySize, SMEM_TOTAL);
    cudaFuncSetAttribute(hgemm<0,true ,false,true ,false,false,true >, cudaFuncAttributeMaxDynamicSharedMemorySize, SMEM_TOTAL);

    const float scale = 1.0f / 32.0f;

    // 1) LN1 -> fp16 (critical path for QKV; launch first)
    ln_half_kernel<<<BSz, 256>>>(x, gamma1, beta1, ln1);

    // 2) merged weight converts fp32 -> fp16 (single launch)
    {
        long total = 3L*Dz*Dz + 2L*(long)Dz*Fz;   // 11534336 elems
        convert_all_kernel<<<(unsigned)(total/1024), 256>>>(
            Qw, Kw, Vw, w1, w2, qw, kw, vw, w1h, w2h);
    }

    // 3) Q, K, V projections -> fp16 (TRB: B = weight [K=D, N=D])
    {
        dim3 grid(Dz/BN, BSz/BM, 1);
        hgemm<1,false,false,false,false,false,true><<<grid, 256, SMEM_TOTAL>>>(
            ln1, qw, nullptr, q, nullptr, nullptr, BSz, Dz, Dz, 1.f, 0, 0, 0);
        hgemm<1,false,false,false,false,false,true><<<grid, 256, SMEM_TOTAL>>>(
            ln1, kw, nullptr, k, nullptr, nullptr, BSz, Dz, Dz, 1.f, 0, 0, 0);
        hgemm<1,false,false,false,false,false,true><<<grid, 256, SMEM_TOTAL>>>(
            ln1, vw, nullptr, vh, nullptr, nullptr, BSz, Dz, Dz, 1.f, 0, 0, 0);
    }

    // 4) scores = Q@K^T * scale (causal tile-skip), fp32 out; B=K fp16 [S,D] K-major
    {
        dim3 grid(Sz/BN, Sz/BM, Bz);
        hgemm<0,false,false,false,true,false,false><<<grid, 256, SMEM_TOTAL>>>(
            q, k, sc, nullptr, nullptr, nullptr,
            Sz, Sz, Dz, scale, (long)Sz*Dz, (long)Sz*Dz, (long)Sz*Sz);
    }

    // 5) causal softmax -> fp16 probs
    softmax_half_kernel<<<BSz, 256>>>(sc, p);

    // 6) x1 = x + P@V (TRB: B = V fp16 [K=S, N=D]; K trimmed by causality)
    {
        dim3 grid(Dz/BN, Sz/BM, Bz);
        hgemm<0,false,false,true,false,true,true><<<grid, 256, SMEM_TOTAL>>>(
            p, vh, x1, nullptr, nullptr, x,
            Sz, Dz, Sz, 1.f, (long)Sz*Sz, (long)Sz*Dz, (long)Sz*Dz);
    }

    // 7) LN2 -> fp16
    ln_half_kernel<<<BSz, 256>>>(x1, gamma2, beta2, ln2);

    // 8) h = relu(ln2 @ w1 + b1) -> fp16 (TRB: B = w1 [K=D, N=F])
    {
        dim3 grid(Fz/BN, BSz/BM, 1);
        hgemm<1,true,true,false,false,false,true><<<grid, 256, SMEM_TOTAL>>>(
            ln2, w1h, nullptr, h, b1, nullptr, BSz, Fz, Dz, 1.f, 0, 0, 0);
    }

    // 9) out = x1 + h @ w2 + b2 (TRB: B = w2 [K=F, N=D])
    {
        dim3 grid(Dz/BN, BSz/BM, 1);
        hgemm<0,true,false,true,false,false,true><<<grid, 256, SMEM_TOTAL>>>(
            h, w2h, out, nullptr, b2, x1, BSz, Dz, Fz, 1.f, 0, 0, 0);
    }
}